// round 8
// baseline (speedup 1.0000x reference)
#include <cuda_runtime.h>
#include <cuda_bf16.h>
#include <math.h>
#include <stdint.h>

// ---------------- problem constants ----------------
#define Bc   2
#define Tc   2048
#define Dc   1024
#define Hc   16
#define HDc  64
#define DFFc 4096
#define Lc   8
#define Vc   50257
#define BTc  (Bc*Tc)          // 4096
#define EPSc 1e-5f

// ---------------- static device scratch (no allocs allowed) ----------------
__device__ float g_h  [BTc*Dc];
__device__ float g_xn [BTc*Dc];
__device__ float g_q  [BTc*Dc];
__device__ float g_k  [BTc*Dc];
__device__ float g_v  [BTc*Dc];
__device__ float g_ctx[BTc*Dc];
__device__ float g_ff [(long)BTc*DFFc];
__device__ float g_fin[Bc*Dc];               // final-LN of last tokens

// ---------------- helpers ----------------
__device__ __forceinline__ float gelu_f(float x) {
    const float c = 0.7978845608028654f;
    return 0.5f * x * (1.0f + tanhf(c * (x + 0.044715f * x * x * x)));
}
__device__ __forceinline__ float tf32r(float x) {
    uint32_t u;
    asm("cvt.rna.tf32.f32 %0, %1;" : "=r"(u) : "f"(x));
    return __uint_as_float(u);
}
__device__ __forceinline__ void mma_tf32(float* c, const uint32_t* a, const uint32_t* b) {
    asm volatile(
        "mma.sync.aligned.m16n8k8.row.col.f32.tf32.tf32.f32 "
        "{%0,%1,%2,%3}, {%4,%5,%6,%7}, {%8,%9}, {%0,%1,%2,%3};"
        : "+f"(c[0]), "+f"(c[1]), "+f"(c[2]), "+f"(c[3])
        : "r"(a[0]), "r"(a[1]), "r"(a[2]), "r"(a[3]), "r"(b[0]), "r"(b[1]));
}

// ---------------- embedding ----------------
__global__ void embed_k(const int* __restrict__ x,
                        const float* __restrict__ Wemb,
                        const float* __restrict__ pos,
                        float* __restrict__ h)
{
    long i = (long)blockIdx.x * blockDim.x + threadIdx.x;
    if (i >= (long)BTc * Dc) return;
    int row = (int)(i / Dc);
    int d   = (int)(i % Dc);
    int t   = row % Tc;
    int tok = x[row];
    h[i] = Wemb[(long)tok * Dc + d] + pos[(long)t * Dc + d];
}

// ---------------- layernorm (ddof=1, std+eps) ----------------
__global__ void ln_k(const float* __restrict__ in, long inStride,
                     float* __restrict__ out, long outStride,
                     const float* __restrict__ sc, const float* __restrict__ sh)
{
    __shared__ float red[256];
    int r = blockIdx.x, tid = threadIdx.x;
    const float* x = in + (long)r * inStride;
    float xv[4];
    float s = 0.f;
#pragma unroll
    for (int i = 0; i < 4; i++) { xv[i] = x[tid + i * 256]; s += xv[i]; }
    red[tid] = s; __syncthreads();
    for (int st = 128; st > 0; st >>= 1) { if (tid < st) red[tid] += red[tid + st]; __syncthreads(); }
    float mean = red[0] * (1.0f / (float)Dc);
    __syncthreads();
    float v = 0.f;
#pragma unroll
    for (int i = 0; i < 4; i++) { float t = xv[i] - mean; v += t * t; }
    red[tid] = v; __syncthreads();
    for (int st = 128; st > 0; st >>= 1) { if (tid < st) red[tid] += red[tid + st]; __syncthreads(); }
    float inv = 1.0f / (sqrtf(red[0] / (float)(Dc - 1)) + EPSc);
    float* o = out + (long)r * outStride;
#pragma unroll
    for (int i = 0; i < 4; i++) { int d = tid + i * 256; o[d] = sc[d] * ((xv[i] - mean) * inv) + sh[d]; }
}

// =====================================================================
// flash_k: fused causal attention for one (b,h,q-tile of 64 rows).
// 128 threads = 4 warps, each warp owns 16 q-rows x full 64 cols.
// Online softmax; S and P never touch global memory.
// Fragment layouts identical to the R5-verified gemm_nt2 scheme.
// =====================================================================
struct SmemMain { float4 k[1024]; float4 v[1024]; float4 p[1024]; };
union SmemU { SmemMain m; float q[64 * 68]; };

__global__ __launch_bounds__(128, 3)
void flash_k(const float* __restrict__ Qg, const float* __restrict__ Kg,
             const float* __restrict__ Vg, float* __restrict__ Og)
{
    __shared__ SmemU sm;

    int qt = (int)gridDim.x - 1 - blockIdx.x;   // reversed: long CTAs first
    int q0 = qt * 64;
    int z  = blockIdx.y;
    int b  = z / Hc, hh = z % Hc;
    long base = (long)b * Tc * Dc + (long)hh * HDc;
    const float* Qb = Qg + base;
    const float* Kb = Kg + base;
    const float* Vb = Vg + base;
    float* Ob = Og + base;

    int tid = threadIdx.x, lane = tid & 31, warp = tid >> 5;
    int g = lane >> 2, c = lane & 3;

    // ---- load Q tile into smem (row stride 68 floats, conflict-free frags) ----
    {
        int kr = tid >> 1, half = tid & 1;
        const float* src = Qb + (long)(q0 + kr) * Dc + half * 32;
        float* dst = sm.q + kr * 68 + half * 32;
#pragma unroll
        for (int f = 0; f < 8; f++)
            *(float4*)(dst + f * 4) = *(const float4*)(src + f * 4);
    }
    __syncthreads();

    // ---- Q fragments in registers (tf32) ----
    uint32_t qf[8][4];
    {
        int r0 = warp * 16 + g;
#pragma unroll
        for (int kb = 0; kb < 8; kb++) {
            int kc = kb * 8 + c;
            qf[kb][0] = __float_as_uint(tf32r(sm.q[r0 * 68 + kc]));
            qf[kb][1] = __float_as_uint(tf32r(sm.q[(r0 + 8) * 68 + kc]));
            qf[kb][2] = __float_as_uint(tf32r(sm.q[r0 * 68 + kc + 4]));
            qf[kb][3] = __float_as_uint(tf32r(sm.q[(r0 + 8) * 68 + kc + 4]));
        }
    }
    __syncthreads();   // union region about to be reused for K/V

    float oacc[8][4];
#pragma unroll
    for (int i = 0; i < 8; i++)
#pragma unroll
        for (int e = 0; e < 4; e++) oacc[i][e] = 0.f;
    float m0 = -1e30f, m1 = -1e30f, l0 = 0.f, l1 = 0.f;

    // staging roles
    int jK  = tid >> 5;            // 0..3  (16-row block of K)
    int gK  = (tid >> 2) & 7;
    int kb2 = tid & 3;
    const float* Kp0 = Kb + (long)(16 * jK + gK) * Dc;
    const float* Kp1 = Kp0 + 8L * Dc;
    int vr = tid >> 1, vh = tid & 1;
    int vkb = vr >> 3, vc8 = vr & 7;
    int vcc = vc8 & 3, vhi = vc8 >> 2;
    int vsw = (vkb >> 1) & 3;

    int nkt = qt + 1;
    for (int kt = 0; kt < nkt; kt++) {
        int k0 = kt * 64;

        // ---- stage K tile into B-fragment slots ----
#pragma unroll
        for (int i = 0; i < 2; i++) {
            int kb = kb2 * 2 + i;
            const float* p0 = Kp0 + (long)k0 * Dc + kb * 8;
            const float* p1 = Kp1 + (long)k0 * Dc + kb * 8;
            float4 a0 = *(const float4*)p0, a1 = *(const float4*)(p0 + 4);
            float4 b0 = *(const float4*)p1, b1 = *(const float4*)(p1 + 4);
            const float* A0 = (const float*)&a0; const float* A1 = (const float*)&a1;
            const float* B0 = (const float*)&b0; const float* B1 = (const float*)&b1;
            int sw = (kb >> 1) & 3;
#pragma unroll
            for (int cc = 0; cc < 4; cc++) {
                int slot = kb * 128 + jK * 32 + ((cc ^ sw) << 3) + gK;
                sm.m.k[slot] = make_float4(tf32r(A0[cc]), tf32r(A1[cc]),
                                           tf32r(B0[cc]), tf32r(B1[cc]));
            }
        }
        // ---- stage V tile, transposed, into B-fragment slots ----
        {
            const float* vsrc = Vb + (long)(k0 + vr) * Dc + vh * 32;
            float* vs = (float*)sm.m.v;
#pragma unroll
            for (int f = 0; f < 8; f++) {
                float4 vv = *(const float4*)(vsrc + f * 4);
                const float* V4 = (const float*)&vv;
#pragma unroll
                for (int e = 0; e < 4; e++) {
                    int d  = vh * 32 + f * 4 + e;
                    int j  = d >> 4, g0 = d & 15;
                    int gg = g0 & 7;
                    int comp = vhi + ((g0 >> 3) << 1);
                    int slot = vkb * 128 + j * 32 + ((vcc ^ vsw) << 3) + gg;
                    vs[slot * 4 + comp] = tf32r(V4[e]);
                }
            }
        }
        __syncthreads();

        // ---- S = Q @ K^T ----
        float sacc[8][4];
#pragma unroll
        for (int i = 0; i < 8; i++)
#pragma unroll
            for (int e = 0; e < 4; e++) sacc[i][e] = 0.f;
#pragma unroll
        for (int kb = 0; kb < 8; kb++) {
            int sw = (kb >> 1) & 3;
            int fb = kb * 128 + ((c ^ sw) << 3) + g;
            float4 bq0 = sm.m.k[fb];
            float4 bq1 = sm.m.k[fb + 32];
            float4 bq2 = sm.m.k[fb + 64];
            float4 bq3 = sm.m.k[fb + 96];
            mma_tf32(sacc[0], qf[kb], (const uint32_t*)&bq0.x);
            mma_tf32(sacc[1], qf[kb], (const uint32_t*)&bq0.z);
            mma_tf32(sacc[2], qf[kb], (const uint32_t*)&bq1.x);
            mma_tf32(sacc[3], qf[kb], (const uint32_t*)&bq1.z);
            mma_tf32(sacc[4], qf[kb], (const uint32_t*)&bq2.x);
            mma_tf32(sacc[5], qf[kb], (const uint32_t*)&bq2.z);
            mma_tf32(sacc[6], qf[kb], (const uint32_t*)&bq3.x);
            mma_tf32(sacc[7], qf[kb], (const uint32_t*)&bq3.z);
        }

        // ---- mask (diagonal tile only), scale, online softmax ----
        bool diag = (kt == nkt - 1);
        int qr0 = q0 + warp * 16 + g;
        int qr1 = qr0 + 8;
        float rm0 = -1e30f, rm1 = -1e30f;
#pragma unroll
        for (int ni = 0; ni < 8; ni++) {
#pragma unroll
            for (int e = 0; e < 4; e++) {
                float vvv = sacc[ni][e] * 0.125f;
                if (diag) {
                    int kc = k0 + ni * 8 + c * 2 + (e & 1);
                    if (kc > ((e >= 2) ? qr1 : qr0)) vvv = -1e30f;
                }
                sacc[ni][e] = vvv;
                if (e < 2) rm0 = fmaxf(rm0, vvv); else rm1 = fmaxf(rm1, vvv);
            }
        }
        rm0 = fmaxf(rm0, __shfl_xor_sync(0xffffffffu, rm0, 1));
        rm0 = fmaxf(rm0, __shfl_xor_sync(0xffffffffu, rm0, 2));
        rm1 = fmaxf(rm1, __shfl_xor_sync(0xffffffffu, rm1, 1));
        rm1 = fmaxf(rm1, __shfl_xor_sync(0xffffffffu, rm1, 2));
        float mn0 = fmaxf(m0, rm0), mn1 = fmaxf(m1, rm1);
        float sc0 = __expf(m0 - mn0), sc1 = __expf(m1 - mn1);
        float rs0 = 0.f, rs1 = 0.f;
#pragma unroll
        for (int ni = 0; ni < 8; ni++) {
#pragma unroll
            for (int e = 0; e < 4; e++) {
                float ee = __expf(sacc[ni][e] - ((e < 2) ? mn0 : mn1));
                sacc[ni][e] = ee;
                if (e < 2) rs0 += ee; else rs1 += ee;
            }
        }
        rs0 += __shfl_xor_sync(0xffffffffu, rs0, 1);
        rs0 += __shfl_xor_sync(0xffffffffu, rs0, 2);
        rs1 += __shfl_xor_sync(0xffffffffu, rs1, 1);
        rs1 += __shfl_xor_sync(0xffffffffu, rs1, 2);
        l0 = l0 * sc0 + rs0;
        l1 = l1 * sc1 + rs1;
        m0 = mn0; m1 = mn1;
#pragma unroll
        for (int ni = 0; ni < 8; ni++) {
#pragma unroll
            for (int e = 0; e < 4; e++) oacc[ni][e] *= (e < 2) ? sc0 : sc1;
        }

        // ---- store P into A-fragment slots (per-warp region) ----
        {
            float* ps = (float*)(sm.m.p + warp * 256);
            int c8a = 2 * c;
            int ccA = c8a & 3, hiA = c8a >> 2;
            int c8b = c8a + 1;
            int ccB = c8b & 3, hiB = c8b >> 2;
#pragma unroll
            for (int ni = 0; ni < 8; ni++) {
                int slotA = ni * 32 + ccA * 8 + g;
                *(float2*)(ps + slotA * 4 + hiA * 2) =
                    make_float2(tf32r(sacc[ni][0]), tf32r(sacc[ni][2]));
                int slotB = ni * 32 + ccB * 8 + g;
                *(float2*)(ps + slotB * 4 + hiB * 2) =
                    make_float2(tf32r(sacc[ni][1]), tf32r(sacc[ni][3]));
            }
        }
        __syncwarp();

        // ---- O += P @ V ----
#pragma unroll
        for (int kb = 0; kb < 8; kb++) {
            float4 pf = sm.m.p[warp * 256 + kb * 32 + c * 8 + g];
            int sw = (kb >> 1) & 3;
            int fb = kb * 128 + ((c ^ sw) << 3) + g;
            float4 bv0 = sm.m.v[fb];
            float4 bv1 = sm.m.v[fb + 32];
            float4 bv2 = sm.m.v[fb + 64];
            float4 bv3 = sm.m.v[fb + 96];
            mma_tf32(oacc[0], (const uint32_t*)&pf, (const uint32_t*)&bv0.x);
            mma_tf32(oacc[1], (const uint32_t*)&pf, (const uint32_t*)&bv0.z);
            mma_tf32(oacc[2], (const uint32_t*)&pf, (const uint32_t*)&bv1.x);
            mma_tf32(oacc[3], (const uint32_t*)&pf, (const uint32_t*)&bv1.z);
            mma_tf32(oacc[4], (const uint32_t*)&pf, (const uint32_t*)&bv2.x);
            mma_tf32(oacc[5], (const uint32_t*)&pf, (const uint32_t*)&bv2.z);
            mma_tf32(oacc[6], (const uint32_t*)&pf, (const uint32_t*)&bv3.x);
            mma_tf32(oacc[7], (const uint32_t*)&pf, (const uint32_t*)&bv3.z);
        }
        __syncthreads();   // all reads of K/V done before next staging
    }

    // ---- normalize + write ctx ----
    float il0 = 1.f / l0, il1 = 1.f / l1;
    int r0 = q0 + warp * 16 + g;
#pragma unroll
    for (int ni = 0; ni < 8; ni++) {
        int d = ni * 8 + 2 * c;
        *(float2*)(Ob + (long)r0 * Dc + d) =
            make_float2(oacc[ni][0] * il0, oacc[ni][1] * il0);
        *(float2*)(Ob + (long)(r0 + 8) * Dc + d) =
            make_float2(oacc[ni][2] * il1, oacc[ni][3] * il1);
    }
}

// ---------------- tf32 mma.sync NT GEMM (R3-proven dense path) ----
#define BM 128
#define BN 128
#define BK 16

__device__ __forceinline__ int slotA_of(int lane) { return lane ^ ((lane >> 2) & 6); }
__device__ __forceinline__ int slotB_of(int lane) { return lane ^ ((lane & 16) >> 3); }

template<bool TRANSB>
__global__ __launch_bounds__(256, 2)
void gemm_tc(const float* __restrict__ A, int lda, long aO1, long aO2,
             const float* __restrict__ B, int ldb, long bO1, long bO2,
             float* __restrict__ C, int ldc, long cO1, long cO2,
             int M, int N, int K,
             const float* __restrict__ bias,
             const float* __restrict__ resid,
             float scale, int doGelu, int causalSkip, int causalKlim, int Hdiv)
{
    int m0 = blockIdx.y * BM;
    int n0 = blockIdx.x * BN;
    if (causalSkip && n0 > m0 + BM - 1) return;

    int z  = blockIdx.z;
    int zb = z / Hdiv, zh = z % Hdiv;
    A += (long)zb * aO1 + (long)zh * aO2;
    B += (long)zb * bO1 + (long)zh * bO2;
    C += (long)zb * cO1 + (long)zh * cO2;
    const float* R = resid ? (resid + (long)zb * cO1 + (long)zh * cO2) : (const float*)0;

    __shared__ float4 sA[2][512];
    __shared__ float2 sB[2][1024];

    int tid  = threadIdx.x;
    int lane = tid & 31, warp = tid >> 5;
    int wm = (warp & 1) * 64;
    int wn = (warp >> 1) * 32;
    int bA0 = wm >> 4;
    int nb0 = wn >> 3;
    int slA = slotA_of(lane);
    int slB = slotB_of(lane);

    float acc[4][4][4];
#pragma unroll
    for (int i = 0; i < 4; i++)
#pragma unroll
        for (int j = 0; j < 4; j++)
#pragma unroll
            for (int r = 0; r < 4; r++) acc[i][j][r] = 0.f;

    int Kend = K;
    if (causalKlim) { int lim = m0 + BM; if (lim < Kend) Kend = lim; }
    int nIter = Kend / BK;

    int am  = tid >> 1;
    int as  = tid & 1;
    int aB  = am >> 4;
    int arr = am & 15;
    int ag  = arr & 7;
    int aRegBase = arr >> 3;
    int aSlot[4];
#pragma unroll
    for (int c = 0; c < 4; c++) aSlot[c] = (ag * 4 + c) ^ (ag & 6);
    const float* Aptr = A + (long)(m0 + am) * lda + as * 8;
    bool aOK = (m0 + am) < M;

    const float* Bptr;
    int bn_nn = 0, bk_nn = 0;
    int bSlot[4];
    if (TRANSB) {
        int bg = arr & 7;
#pragma unroll
        for (int c = 0; c < 4; c++) bSlot[c] = (bg * 4 + c) ^ ((bg & 4) >> 1);
        Bptr = B + (long)(n0 + am) * ldb + as * 8;
    } else {
        bk_nn = tid >> 4;
        bn_nn = (tid & 15) * 8;
#pragma unroll
        for (int j = 0; j < 4; j++) bSlot[j] = 0;
        Bptr = B + (long)bk_nn * ldb + n0 + bn_nn;
    }
    bool bOK = TRANSB ? ((n0 + am) < N) : true;

    float4 pa0, pa1, pb0, pb1;
    {
        pa0 = make_float4(0,0,0,0); pa1 = pa0;
        if (aOK) { pa0 = *(const float4*)(Aptr); pa1 = *(const float4*)(Aptr + 4); }
        pb0 = make_float4(0,0,0,0); pb1 = pb0;
        if (TRANSB) {
            if (bOK) { pb0 = *(const float4*)(Bptr); pb1 = *(const float4*)(Bptr + 4); }
        } else {
            if (n0 + bn_nn     < N) pb0 = *(const float4*)(Bptr);
            if (n0 + bn_nn + 4 < N) pb1 = *(const float4*)(Bptr + 4);
        }
    }
    {
        float va[8] = {pa0.x,pa0.y,pa0.z,pa0.w,pa1.x,pa1.y,pa1.z,pa1.w};
        float* baseA = (float*)&sA[0][(as * 8 + aB) * 32];
#pragma unroll
        for (int kk = 0; kk < 8; kk++)
            baseA[aSlot[kk & 3] * 4 + aRegBase + 2 * (kk >> 2)] = tf32r(va[kk]);
        if (TRANSB) {
            float vb[8] = {pb0.x,pb0.y,pb0.z,pb0.w,pb1.x,pb1.y,pb1.z,pb1.w};
            float2* baseB = &sB[0][(as * 16 + aB * 2 + (arr >> 3)) * 32];
#pragma unroll
            for (int kk = 0; kk < 4; kk++)
                baseB[bSlot[kk]] = make_float2(tf32r(vb[kk]), tf32r(vb[kk + 4]));
        } else {
            float vb[8] = {pb0.x,pb0.y,pb0.z,pb0.w,pb1.x,pb1.y,pb1.z,pb1.w};
            int s  = bk_nn >> 3, kk = bk_nn & 7, c = kk & 3, reg = kk >> 2;
            int nb = bn_nn >> 3;
            float* baseB = (float*)&sB[0][(s * 16 + nb) * 32];
#pragma unroll
            for (int j = 0; j < 8; j++) {
                int slot = (j * 4 + c) ^ ((j & 4) >> 1);
                baseB[slot * 2 + reg] = tf32r(vb[j]);
            }
        }
    }
    __syncthreads();

    for (int it = 0; it < nIter; it++) {
        int cur = it & 1;
        bool more = (it + 1) < nIter;
        if (more) {
            long ko = (long)(it + 1) * BK;
            pa0 = make_float4(0,0,0,0); pa1 = pa0;
            if (aOK) { pa0 = *(const float4*)(Aptr + ko); pa1 = *(const float4*)(Aptr + ko + 4); }
            pb0 = make_float4(0,0,0,0); pb1 = pb0;
            if (TRANSB) {
                if (bOK) { pb0 = *(const float4*)(Bptr + ko); pb1 = *(const float4*)(Bptr + ko + 4); }
            } else {
                const float* bp = Bptr + ko * ldb;
                if (n0 + bn_nn     < N) pb0 = *(const float4*)(bp);
                if (n0 + bn_nn + 4 < N) pb1 = *(const float4*)(bp + 4);
            }
        }

#pragma unroll
        for (int s = 0; s < 2; s++) {
            float4 af[4]; float2 bf[4];
#pragma unroll
            for (int mi = 0; mi < 4; mi++) af[mi] = sA[cur][(s * 8 + bA0 + mi) * 32 + slA];
#pragma unroll
            for (int ni = 0; ni < 4; ni++) bf[ni] = sB[cur][(s * 16 + nb0 + ni) * 32 + slB];
#pragma unroll
            for (int mi = 0; mi < 4; mi++)
#pragma unroll
                for (int ni = 0; ni < 4; ni++)
                    mma_tf32(acc[mi][ni], (const uint32_t*)&af[mi], (const uint32_t*)&bf[ni]);
        }

        if (more) {
            int nxt = cur ^ 1;
            float va[8] = {pa0.x,pa0.y,pa0.z,pa0.w,pa1.x,pa1.y,pa1.z,pa1.w};
            float* baseA = (float*)&sA[nxt][(as * 8 + aB) * 32];
#pragma unroll
            for (int kk = 0; kk < 8; kk++)
                baseA[aSlot[kk & 3] * 4 + aRegBase + 2 * (kk >> 2)] = tf32r(va[kk]);
            float vb[8] = {pb0.x,pb0.y,pb0.z,pb0.w,pb1.x,pb1.y,pb1.z,pb1.w};
            if (TRANSB) {
                float2* baseB = &sB[nxt][(as * 16 + aB * 2 + (arr >> 3)) * 32];
#pragma unroll
                for (int kk = 0; kk < 4; kk++)
                    baseB[bSlot[kk]] = make_float2(tf32r(vb[kk]), tf32r(vb[kk + 4]));
            } else {
                int s  = bk_nn >> 3, kk = bk_nn & 7, c = kk & 3, reg = kk >> 2;
                int nb = bn_nn >> 3;
                float* baseB = (float*)&sB[nxt][(s * 16 + nb) * 32];
#pragma unroll
                for (int j = 0; j < 8; j++) {
                    int slot = (j * 4 + c) ^ ((j & 4) >> 1);
                    baseB[slot * 2 + reg] = tf32r(vb[j]);
                }
            }
        }
        __syncthreads();
    }

    int g = lane >> 2, c2 = (lane & 3) * 2;
#pragma unroll
    for (int mi = 0; mi < 4; mi++) {
#pragma unroll
        for (int ni = 0; ni < 4; ni++) {
            int r0 = m0 + wm + mi * 16 + g;
            int cn = n0 + wn + ni * 8 + c2;
#pragma unroll
            for (int e = 0; e < 4; e++) {
                int gm = r0 + (e >= 2 ? 8 : 0);
                int gn = cn + (e & 1);
                if (gm >= M || gn >= N) continue;
                float vv = acc[mi][ni][e] * scale;
                if (bias)   vv += bias[gn];
                if (doGelu) vv = gelu_f(vv);
                if (R)      vv += R[(long)gm * ldc + gn];
                C[(long)gm * ldc + gn] = vv;
            }
        }
    }
}

// ---------------- dedicated logits kernel (M=2, fp32, memory-bound) ----------
__global__ __launch_bounds__(256)
void logits_k(const float* __restrict__ fin,
              const float* __restrict__ Wemb,
              float* __restrict__ out)
{
    __shared__ float f0[Dc], f1[Dc];
    int tid = threadIdx.x;
    for (int i = tid; i < Dc; i += 256) { f0[i] = fin[i]; f1[i] = fin[Dc + i]; }
    __syncthreads();
    int warp = tid >> 5, lane = tid & 31;
    long v = (long)blockIdx.x * 8 + warp;
    if (v >= Vc) return;
    const float* w = Wemb + v * Dc;
    float d0 = 0.f, d1 = 0.f;
    for (int i = lane * 4; i < Dc; i += 128) {
        float4 wv = *(const float4*)(w + i);
        d0 += wv.x * f0[i] + wv.y * f0[i+1] + wv.z * f0[i+2] + wv.w * f0[i+3];
        d1 += wv.x * f1[i] + wv.y * f1[i+1] + wv.z * f1[i+2] + wv.w * f1[i+3];
    }
#pragma unroll
    for (int o = 16; o > 0; o >>= 1) {
        d0 += __shfl_xor_sync(0xffffffff, d0, o);
        d1 += __shfl_xor_sync(0xffffffff, d1, o);
    }
    if (lane == 0) { out[v] = d0; out[(long)Vc + v] = d1; }
}

// ---------------- host-side launch helper ----------------
static inline void launch_nt(const float* A, int lda,
                             const float* B, int ldb,
                             float* C, int ldc,
                             int M, int N, int K,
                             const float* bias, const float* resid,
                             float scale, int gelu)
{
    dim3 g((N + BN - 1) / BN, (M + BM - 1) / BM, 1);
    gemm_tc<true><<<g, 256>>>(A, lda, 0, 0, B, ldb, 0, 0, C, ldc, 0, 0,
                              M, N, K, bias, resid, scale, gelu, 0, 0, 1);
}

extern "C" void kernel_launch(void* const* d_in, const int* in_sizes, int n_in,
                              void* d_out, int out_size)
{
    const int*   x    = (const int*)  d_in[0];
    const float* Wemb = (const float*)d_in[1];
    const float* pos  = (const float*)d_in[2];
    const float* Wq   = (const float*)d_in[3];
    const float* Wk   = (const float*)d_in[4];
    const float* Wv   = (const float*)d_in[5];
    const float* Wo   = (const float*)d_in[6];
    const float* bo   = (const float*)d_in[7];
    const float* n1s  = (const float*)d_in[8];
    const float* n1b  = (const float*)d_in[9];
    const float* n2s  = (const float*)d_in[10];
    const float* n2b  = (const float*)d_in[11];
    const float* W1   = (const float*)d_in[12];
    const float* b1   = (const float*)d_in[13];
    const float* W2   = (const float*)d_in[14];
    const float* b2   = (const float*)d_in[15];
    const float* fs   = (const float*)d_in[16];
    const float* fb   = (const float*)d_in[17];
    float* out = (float*)d_out;

    float *h, *xn, *q, *k, *v, *ctx, *ff, *fin;
    cudaGetSymbolAddress((void**)&h,   g_h);
    cudaGetSymbolAddress((void**)&xn,  g_xn);
    cudaGetSymbolAddress((void**)&q,   g_q);
    cudaGetSymbolAddress((void**)&k,   g_k);
    cudaGetSymbolAddress((void**)&v,   g_v);
    cudaGetSymbolAddress((void**)&ctx, g_ctx);
    cudaGetSymbolAddress((void**)&ff,  g_ff);
    cudaGetSymbolAddress((void**)&fin, g_fin);

    const long TD = (long)Tc * Dc;

    {
        long n = (long)BTc * Dc;
        embed_k<<<(unsigned)((n + 255) / 256), 256>>>(x, Wemb, pos, h);
    }

    for (int l = 0; l < Lc; l++) {
        const float* Wql = Wq + (long)l * Dc * Dc;
        const float* Wkl = Wk + (long)l * Dc * Dc;
        const float* Wvl = Wv + (long)l * Dc * Dc;
        const float* Wol = Wo + (long)l * Dc * Dc;
        const float* bol = bo + (long)l * Dc;
        const float* W1l = W1 + (long)l * DFFc * Dc;
        const float* b1l = b1 + (long)l * DFFc;
        const float* W2l = W2 + (long)l * Dc * DFFc;
        const float* b2l = b2 + (long)l * Dc;

        // LN1
        ln_k<<<BTc, 256>>>(h, Dc, xn, Dc, n1s + (long)l * Dc, n1b + (long)l * Dc);

        // Q,K,V = xn @ W^T
        launch_nt(xn, Dc, Wql, Dc, q, Dc, BTc, Dc, Dc, 0, 0, 1.f, 0);
        launch_nt(xn, Dc, Wkl, Dc, k, Dc, BTc, Dc, Dc, 0, 0, 1.f, 0);
        launch_nt(xn, Dc, Wvl, Dc, v, Dc, BTc, Dc, Dc, 0, 0, 1.f, 0);

        // fused causal attention: ctx = softmax(mask(QK^T)/8) @ V
        {
            dim3 fg(Tc / 64, Bc * Hc);
            flash_k<<<fg, 128>>>(q, k, v, ctx);
        }

        // h = h + ctx @ Wo^T + bo
        launch_nt(ctx, Dc, Wol, Dc, h, Dc, BTc, Dc, Dc, bol, h, 1.f, 0);

        // LN2
        ln_k<<<BTc, 256>>>(h, Dc, xn, Dc, n2s + (long)l * Dc, n2b + (long)l * Dc);

        // ff = gelu(xn @ W1^T + b1)
        launch_nt(xn, Dc, W1l, Dc, ff, DFFc, BTc, DFFc, Dc, b1l, 0, 1.f, 1);

        // h = h + ff @ W2^T + b2
        launch_nt(ff, DFFc, W2l, DFFc, h, Dc, BTc, Dc, DFFc, b2l, h, 1.f, 0);
    }

    // final LN on the 2 last-token rows only
    ln_k<<<Bc, 256>>>(h + (long)(Tc - 1) * Dc, TD, fin, Dc, fs, fb);

    // logits (fp32, memory-bound dedicated kernel)
    logits_k<<<(Vc + 7) / 8, 256>>>(fin, Wemb, out);
}

// round 9
// speedup vs baseline: 1.0381x; 1.0381x over previous
#include <cuda_runtime.h>
#include <cuda_bf16.h>
#include <math.h>
#include <stdint.h>

// ---------------- problem constants ----------------
#define Bc   2
#define Tc   2048
#define Dc   1024
#define Hc   16
#define HDc  64
#define DFFc 4096
#define Lc   8
#define Vc   50257
#define BTc  (Bc*Tc)          // 4096
#define EPSc 1e-5f

// ---------------- static device scratch (no allocs allowed) ----------------
__device__ float g_h  [BTc*Dc];
__device__ float g_xn [BTc*Dc];
__device__ float g_q  [BTc*Dc];
__device__ float g_k  [BTc*Dc];
__device__ float g_v  [BTc*Dc];
__device__ float g_ctx[BTc*Dc];
__device__ float g_ff [(long)BTc*DFFc];
__device__ float g_fin[Bc*Dc];               // final-LN of last tokens

// ---------------- helpers ----------------
__device__ __forceinline__ float gelu_f(float x) {
    const float c = 0.7978845608028654f;
    return 0.5f * x * (1.0f + tanhf(c * (x + 0.044715f * x * x * x)));
}
__device__ __forceinline__ float tf32r(float x) {
    uint32_t u;
    asm("cvt.rna.tf32.f32 %0, %1;" : "=r"(u) : "f"(x));
    return __uint_as_float(u);
}
__device__ __forceinline__ void mma_tf32(float* c, const uint32_t* a, const uint32_t* b) {
    asm volatile(
        "mma.sync.aligned.m16n8k8.row.col.f32.tf32.tf32.f32 "
        "{%0,%1,%2,%3}, {%4,%5,%6,%7}, {%8,%9}, {%0,%1,%2,%3};"
        : "+f"(c[0]), "+f"(c[1]), "+f"(c[2]), "+f"(c[3])
        : "r"(a[0]), "r"(a[1]), "r"(a[2]), "r"(a[3]), "r"(b[0]), "r"(b[1]));
}

// ---------------- embedding ----------------
__global__ void embed_k(const int* __restrict__ x,
                        const float* __restrict__ Wemb,
                        const float* __restrict__ pos,
                        float* __restrict__ h)
{
    long i = (long)blockIdx.x * blockDim.x + threadIdx.x;
    if (i >= (long)BTc * Dc) return;
    int row = (int)(i / Dc);
    int d   = (int)(i % Dc);
    int t   = row % Tc;
    int tok = x[row];
    h[i] = Wemb[(long)tok * Dc + d] + pos[(long)t * Dc + d];
}

// ---------------- layernorm (ddof=1, std+eps) ----------------
__global__ void ln_k(const float* __restrict__ in, long inStride,
                     float* __restrict__ out, long outStride,
                     const float* __restrict__ sc, const float* __restrict__ sh)
{
    __shared__ float red[256];
    int r = blockIdx.x, tid = threadIdx.x;
    const float* x = in + (long)r * inStride;
    float xv[4];
    float s = 0.f;
#pragma unroll
    for (int i = 0; i < 4; i++) { xv[i] = x[tid + i * 256]; s += xv[i]; }
    red[tid] = s; __syncthreads();
    for (int st = 128; st > 0; st >>= 1) { if (tid < st) red[tid] += red[tid + st]; __syncthreads(); }
    float mean = red[0] * (1.0f / (float)Dc);
    __syncthreads();
    float v = 0.f;
#pragma unroll
    for (int i = 0; i < 4; i++) { float t = xv[i] - mean; v += t * t; }
    red[tid] = v; __syncthreads();
    for (int st = 128; st > 0; st >>= 1) { if (tid < st) red[tid] += red[tid + st]; __syncthreads(); }
    float inv = 1.0f / (sqrtf(red[0] / (float)(Dc - 1)) + EPSc);
    float* o = out + (long)r * outStride;
#pragma unroll
    for (int i = 0; i < 4; i++) { int d = tid + i * 256; o[d] = sc[d] * ((xv[i] - mean) * inv) + sh[d]; }
}

// =====================================================================
// flash_k v2: fused causal attention, q-tile = 128 rows, 256 threads.
// 8 warps x 16 q-rows; k-tiles of 64. K staged by threads 0-127,
// V by threads 128-255 (R8-verified fragment-slot layouts).
// No launch_bounds min-blocks -> no register spills.
// Dynamic smem 64KB: K 16K | V 16K | P 32K (Q load area unioned on top).
// =====================================================================
__global__ __launch_bounds__(256)
void flash_k(const float* __restrict__ Qg, const float* __restrict__ Kg,
             const float* __restrict__ Vg, float* __restrict__ Og)
{
    extern __shared__ float4 dsm[];
    float4* Ks = dsm;            // [1024]
    float4* Vs = dsm + 1024;     // [1024]
    float4* Ps = dsm + 2048;     // [2048] (8 warps x 256)
    float*  Qs = (float*)dsm;    // [128*68] transient (consumed before staging)

    int qt = (int)gridDim.x - 1 - blockIdx.x;   // reversed: long CTAs first
    int q0 = qt * 128;
    int z  = blockIdx.y;
    int b  = z / Hc, hh = z % Hc;
    long base = (long)b * Tc * Dc + (long)hh * HDc;
    const float* Qb = Qg + base;
    const float* Kb = Kg + base;
    const float* Vb = Vg + base;
    float* Ob = Og + base;

    int tid = threadIdx.x, lane = tid & 31, warp = tid >> 5;   // warp 0..7
    int g = lane >> 2, c = lane & 3;

    // ---- load Q tile (128 x 64) into smem, stride 68 ----
    {
        int kr = tid >> 1, half = tid & 1;
        const float* src = Qb + (long)(q0 + kr) * Dc + half * 32;
        float* dst = Qs + kr * 68 + half * 32;
#pragma unroll
        for (int f = 0; f < 8; f++)
            *(float4*)(dst + f * 4) = *(const float4*)(src + f * 4);
    }
    __syncthreads();

    // ---- Q fragments (tf32) ----
    uint32_t qf[8][4];
    {
        int r0w = warp * 16 + g;
#pragma unroll
        for (int kb = 0; kb < 8; kb++) {
            int kc = kb * 8 + c;
            qf[kb][0] = __float_as_uint(tf32r(Qs[r0w * 68 + kc]));
            qf[kb][1] = __float_as_uint(tf32r(Qs[(r0w + 8) * 68 + kc]));
            qf[kb][2] = __float_as_uint(tf32r(Qs[r0w * 68 + kc + 4]));
            qf[kb][3] = __float_as_uint(tf32r(Qs[(r0w + 8) * 68 + kc + 4]));
        }
    }
    __syncthreads();   // Q area about to be overwritten by K/V/P

    float oacc[8][4];
#pragma unroll
    for (int i = 0; i < 8; i++)
#pragma unroll
        for (int e = 0; e < 4; e++) oacc[i][e] = 0.f;
    float m0 = -1e30f, m1 = -1e30f, l0 = 0.f, l1 = 0.f;

    // staging roles: threads 0-127 stage K, 128-255 stage V
    bool isK = tid < 128;
    int t = isK ? tid : (tid - 128);
    // K role
    int jK  = t >> 5;
    int gK  = (t >> 2) & 7;
    int kb2 = t & 3;
    const float* Kp0 = Kb + (long)(16 * jK + gK) * Dc;
    const float* Kp1 = Kp0 + 8L * Dc;
    // V role
    int vr = t >> 1, vh = t & 1;
    int vkb = vr >> 3, vc8 = vr & 7;
    int vcc = vc8 & 3, vhi = vc8 >> 2;
    int vsw = (vkb >> 1) & 3;

    int nkt = 2 * qt + 2;
    for (int kt = 0; kt < nkt; kt++) {
        int k0 = kt * 64;

        if (isK) {
            // ---- stage K tile into B-fragment slots ----
#pragma unroll
            for (int i = 0; i < 2; i++) {
                int kb = kb2 * 2 + i;
                const float* p0 = Kp0 + (long)k0 * Dc + kb * 8;
                const float* p1 = Kp1 + (long)k0 * Dc + kb * 8;
                float4 a0 = *(const float4*)p0, a1 = *(const float4*)(p0 + 4);
                float4 b0 = *(const float4*)p1, b1 = *(const float4*)(p1 + 4);
                const float* A0 = (const float*)&a0; const float* A1 = (const float*)&a1;
                const float* B0 = (const float*)&b0; const float* B1 = (const float*)&b1;
                int sw = (kb >> 1) & 3;
#pragma unroll
                for (int cc = 0; cc < 4; cc++) {
                    int slot = kb * 128 + jK * 32 + ((cc ^ sw) << 3) + gK;
                    Ks[slot] = make_float4(tf32r(A0[cc]), tf32r(A1[cc]),
                                           tf32r(B0[cc]), tf32r(B1[cc]));
                }
            }
        } else {
            // ---- stage V tile, transposed, into B-fragment slots ----
            const float* vsrc = Vb + (long)(k0 + vr) * Dc + vh * 32;
            float* vs = (float*)Vs;
#pragma unroll
            for (int f = 0; f < 8; f++) {
                float4 vv = *(const float4*)(vsrc + f * 4);
                const float* V4 = (const float*)&vv;
#pragma unroll
                for (int e = 0; e < 4; e++) {
                    int d  = vh * 32 + f * 4 + e;
                    int j  = d >> 4, g0 = d & 15;
                    int gg = g0 & 7;
                    int comp = vhi + ((g0 >> 3) << 1);
                    int slot = vkb * 128 + j * 32 + ((vcc ^ vsw) << 3) + gg;
                    vs[slot * 4 + comp] = tf32r(V4[e]);
                }
            }
        }
        __syncthreads();

        // skip tiles entirely above this warp's diagonal (fully masked)
        bool active = (k0 <= q0 + warp * 16 + 15);
        if (active) {
            // ---- S = Q @ K^T ----
            float sacc[8][4];
#pragma unroll
            for (int i = 0; i < 8; i++)
#pragma unroll
                for (int e = 0; e < 4; e++) sacc[i][e] = 0.f;
#pragma unroll
            for (int kb = 0; kb < 8; kb++) {
                int sw = (kb >> 1) & 3;
                int fb = kb * 128 + ((c ^ sw) << 3) + g;
                float4 bq0 = Ks[fb];
                float4 bq1 = Ks[fb + 32];
                float4 bq2 = Ks[fb + 64];
                float4 bq3 = Ks[fb + 96];
                mma_tf32(sacc[0], qf[kb], (const uint32_t*)&bq0.x);
                mma_tf32(sacc[1], qf[kb], (const uint32_t*)&bq0.z);
                mma_tf32(sacc[2], qf[kb], (const uint32_t*)&bq1.x);
                mma_tf32(sacc[3], qf[kb], (const uint32_t*)&bq1.z);
                mma_tf32(sacc[4], qf[kb], (const uint32_t*)&bq2.x);
                mma_tf32(sacc[5], qf[kb], (const uint32_t*)&bq2.z);
                mma_tf32(sacc[6], qf[kb], (const uint32_t*)&bq3.x);
                mma_tf32(sacc[7], qf[kb], (const uint32_t*)&bq3.z);
            }

            // ---- mask (tiles overlapping diagonal), scale, online softmax ----
            int qr0 = q0 + warp * 16 + g;
            int qr1 = qr0 + 8;
            bool maskNeed = (k0 + 63 > q0 + warp * 16);
            float rm0 = -1e30f, rm1 = -1e30f;
#pragma unroll
            for (int ni = 0; ni < 8; ni++) {
#pragma unroll
                for (int e = 0; e < 4; e++) {
                    float vvv = sacc[ni][e] * 0.125f;
                    if (maskNeed) {
                        int kc = k0 + ni * 8 + c * 2 + (e & 1);
                        if (kc > ((e >= 2) ? qr1 : qr0)) vvv = -1e30f;
                    }
                    sacc[ni][e] = vvv;
                    if (e < 2) rm0 = fmaxf(rm0, vvv); else rm1 = fmaxf(rm1, vvv);
                }
            }
            rm0 = fmaxf(rm0, __shfl_xor_sync(0xffffffffu, rm0, 1));
            rm0 = fmaxf(rm0, __shfl_xor_sync(0xffffffffu, rm0, 2));
            rm1 = fmaxf(rm1, __shfl_xor_sync(0xffffffffu, rm1, 1));
            rm1 = fmaxf(rm1, __shfl_xor_sync(0xffffffffu, rm1, 2));
            float mn0 = fmaxf(m0, rm0), mn1 = fmaxf(m1, rm1);
            float sc0 = __expf(m0 - mn0), sc1 = __expf(m1 - mn1);
            float rs0 = 0.f, rs1 = 0.f;
#pragma unroll
            for (int ni = 0; ni < 8; ni++) {
#pragma unroll
                for (int e = 0; e < 4; e++) {
                    float ee = __expf(sacc[ni][e] - ((e < 2) ? mn0 : mn1));
                    sacc[ni][e] = ee;
                    if (e < 2) rs0 += ee; else rs1 += ee;
                }
            }
            rs0 += __shfl_xor_sync(0xffffffffu, rs0, 1);
            rs0 += __shfl_xor_sync(0xffffffffu, rs0, 2);
            rs1 += __shfl_xor_sync(0xffffffffu, rs1, 1);
            rs1 += __shfl_xor_sync(0xffffffffu, rs1, 2);
            l0 = l0 * sc0 + rs0;
            l1 = l1 * sc1 + rs1;
            m0 = mn0; m1 = mn1;
#pragma unroll
            for (int ni = 0; ni < 8; ni++) {
#pragma unroll
                for (int e = 0; e < 4; e++) oacc[ni][e] *= (e < 2) ? sc0 : sc1;
            }

            // ---- store P into A-fragment slots (per-warp region) ----
            {
                float* ps = (float*)(Ps + warp * 256);
                int c8a = 2 * c;
                int ccA = c8a & 3, hiA = c8a >> 2;
                int c8b = c8a + 1;
                int ccB = c8b & 3, hiB = c8b >> 2;
#pragma unroll
                for (int ni = 0; ni < 8; ni++) {
                    int slotA = ni * 32 + ccA * 8 + g;
                    *(float2*)(ps + slotA * 4 + hiA * 2) =
                        make_float2(tf32r(sacc[ni][0]), tf32r(sacc[ni][2]));
                    int slotB = ni * 32 + ccB * 8 + g;
                    *(float2*)(ps + slotB * 4 + hiB * 2) =
                        make_float2(tf32r(sacc[ni][1]), tf32r(sacc[ni][3]));
                }
            }
            __syncwarp();

            // ---- O += P @ V ----
#pragma unroll
            for (int kb = 0; kb < 8; kb++) {
                float4 pf = Ps[warp * 256 + kb * 32 + c * 8 + g];
                int sw = (kb >> 1) & 3;
                int fb = kb * 128 + ((c ^ sw) << 3) + g;
                float4 bv0 = Vs[fb];
                float4 bv1 = Vs[fb + 32];
                float4 bv2 = Vs[fb + 64];
                float4 bv3 = Vs[fb + 96];
                mma_tf32(oacc[0], (const uint32_t*)&pf, (const uint32_t*)&bv0.x);
                mma_tf32(oacc[1], (const uint32_t*)&pf, (const uint32_t*)&bv0.z);
                mma_tf32(oacc[2], (const uint32_t*)&pf, (const uint32_t*)&bv1.x);
                mma_tf32(oacc[3], (const uint32_t*)&pf, (const uint32_t*)&bv1.z);
                mma_tf32(oacc[4], (const uint32_t*)&pf, (const uint32_t*)&bv2.x);
                mma_tf32(oacc[5], (const uint32_t*)&pf, (const uint32_t*)&bv2.z);
                mma_tf32(oacc[6], (const uint32_t*)&pf, (const uint32_t*)&bv3.x);
                mma_tf32(oacc[7], (const uint32_t*)&pf, (const uint32_t*)&bv3.z);
            }
        }
        __syncthreads();   // all reads of K/V done before next staging
    }

    // ---- normalize + write ctx ----
    float il0 = 1.f / l0, il1 = 1.f / l1;
    int r0 = q0 + warp * 16 + g;
#pragma unroll
    for (int ni = 0; ni < 8; ni++) {
        int d = ni * 8 + 2 * c;
        *(float2*)(Ob + (long)r0 * Dc + d) =
            make_float2(oacc[ni][0] * il0, oacc[ni][1] * il0);
        *(float2*)(Ob + (long)(r0 + 8) * Dc + d) =
            make_float2(oacc[ni][2] * il1, oacc[ni][3] * il1);
    }
}

// ---------------- tf32 mma.sync NT GEMM (R3-proven dense path) ----
#define BM 128
#define BN 128
#define BK 16

__device__ __forceinline__ int slotA_of(int lane) { return lane ^ ((lane >> 2) & 6); }
__device__ __forceinline__ int slotB_of(int lane) { return lane ^ ((lane & 16) >> 3); }

template<bool TRANSB>
__global__ __launch_bounds__(256, 2)
void gemm_tc(const float* __restrict__ A, int lda, long aO1, long aO2,
             const float* __restrict__ B, int ldb, long bO1, long bO2,
             float* __restrict__ C, int ldc, long cO1, long cO2,
             int M, int N, int K,
             const float* __restrict__ bias,
             const float* __restrict__ resid,
             float scale, int doGelu, int causalSkip, int causalKlim, int Hdiv)
{
    int m0 = blockIdx.y * BM;
    int n0 = blockIdx.x * BN;
    if (causalSkip && n0 > m0 + BM - 1) return;

    int z  = blockIdx.z;
    int zb = z / Hdiv, zh = z % Hdiv;
    A += (long)zb * aO1 + (long)zh * aO2;
    B += (long)zb * bO1 + (long)zh * bO2;
    C += (long)zb * cO1 + (long)zh * cO2;
    const float* R = resid ? (resid + (long)zb * cO1 + (long)zh * cO2) : (const float*)0;

    __shared__ float4 sA[2][512];
    __shared__ float2 sB[2][1024];

    int tid  = threadIdx.x;
    int lane = tid & 31, warp = tid >> 5;
    int wm = (warp & 1) * 64;
    int wn = (warp >> 1) * 32;
    int bA0 = wm >> 4;
    int nb0 = wn >> 3;
    int slA = slotA_of(lane);
    int slB = slotB_of(lane);

    float acc[4][4][4];
#pragma unroll
    for (int i = 0; i < 4; i++)
#pragma unroll
        for (int j = 0; j < 4; j++)
#pragma unroll
            for (int r = 0; r < 4; r++) acc[i][j][r] = 0.f;

    int Kend = K;
    if (causalKlim) { int lim = m0 + BM; if (lim < Kend) Kend = lim; }
    int nIter = Kend / BK;

    int am  = tid >> 1;
    int as  = tid & 1;
    int aB  = am >> 4;
    int arr = am & 15;
    int ag  = arr & 7;
    int aRegBase = arr >> 3;
    int aSlot[4];
#pragma unroll
    for (int c = 0; c < 4; c++) aSlot[c] = (ag * 4 + c) ^ (ag & 6);
    const float* Aptr = A + (long)(m0 + am) * lda + as * 8;
    bool aOK = (m0 + am) < M;

    const float* Bptr;
    int bn_nn = 0, bk_nn = 0;
    int bSlot[4];
    if (TRANSB) {
        int bg = arr & 7;
#pragma unroll
        for (int c = 0; c < 4; c++) bSlot[c] = (bg * 4 + c) ^ ((bg & 4) >> 1);
        Bptr = B + (long)(n0 + am) * ldb + as * 8;
    } else {
        bk_nn = tid >> 4;
        bn_nn = (tid & 15) * 8;
#pragma unroll
        for (int j = 0; j < 4; j++) bSlot[j] = 0;
        Bptr = B + (long)bk_nn * ldb + n0 + bn_nn;
    }
    bool bOK = TRANSB ? ((n0 + am) < N) : true;

    float4 pa0, pa1, pb0, pb1;
    {
        pa0 = make_float4(0,0,0,0); pa1 = pa0;
        if (aOK) { pa0 = *(const float4*)(Aptr); pa1 = *(const float4*)(Aptr + 4); }
        pb0 = make_float4(0,0,0,0); pb1 = pb0;
        if (TRANSB) {
            if (bOK) { pb0 = *(const float4*)(Bptr); pb1 = *(const float4*)(Bptr + 4); }
        } else {
            if (n0 + bn_nn     < N) pb0 = *(const float4*)(Bptr);
            if (n0 + bn_nn + 4 < N) pb1 = *(const float4*)(Bptr + 4);
        }
    }
    {
        float va[8] = {pa0.x,pa0.y,pa0.z,pa0.w,pa1.x,pa1.y,pa1.z,pa1.w};
        float* baseA = (float*)&sA[0][(as * 8 + aB) * 32];
#pragma unroll
        for (int kk = 0; kk < 8; kk++)
            baseA[aSlot[kk & 3] * 4 + aRegBase + 2 * (kk >> 2)] = tf32r(va[kk]);
        if (TRANSB) {
            float vb[8] = {pb0.x,pb0.y,pb0.z,pb0.w,pb1.x,pb1.y,pb1.z,pb1.w};
            float2* baseB = &sB[0][(as * 16 + aB * 2 + (arr >> 3)) * 32];
#pragma unroll
            for (int kk = 0; kk < 4; kk++)
                baseB[bSlot[kk]] = make_float2(tf32r(vb[kk]), tf32r(vb[kk + 4]));
        } else {
            float vb[8] = {pb0.x,pb0.y,pb0.z,pb0.w,pb1.x,pb1.y,pb1.z,pb1.w};
            int s  = bk_nn >> 3, kk = bk_nn & 7, c = kk & 3, reg = kk >> 2;
            int nb = bn_nn >> 3;
            float* baseB = (float*)&sB[0][(s * 16 + nb) * 32];
#pragma unroll
            for (int j = 0; j < 8; j++) {
                int slot = (j * 4 + c) ^ ((j & 4) >> 1);
                baseB[slot * 2 + reg] = tf32r(vb[j]);
            }
        }
    }
    __syncthreads();

    for (int it = 0; it < nIter; it++) {
        int cur = it & 1;
        bool more = (it + 1) < nIter;
        if (more) {
            long ko = (long)(it + 1) * BK;
            pa0 = make_float4(0,0,0,0); pa1 = pa0;
            if (aOK) { pa0 = *(const float4*)(Aptr + ko); pa1 = *(const float4*)(Aptr + ko + 4); }
            pb0 = make_float4(0,0,0,0); pb1 = pb0;
            if (TRANSB) {
                if (bOK) { pb0 = *(const float4*)(Bptr + ko); pb1 = *(const float4*)(Bptr + ko + 4); }
            } else {
                const float* bp = Bptr + ko * ldb;
                if (n0 + bn_nn     < N) pb0 = *(const float4*)(bp);
                if (n0 + bn_nn + 4 < N) pb1 = *(const float4*)(bp + 4);
            }
        }

#pragma unroll
        for (int s = 0; s < 2; s++) {
            float4 af[4]; float2 bf[4];
#pragma unroll
            for (int mi = 0; mi < 4; mi++) af[mi] = sA[cur][(s * 8 + bA0 + mi) * 32 + slA];
#pragma unroll
            for (int ni = 0; ni < 4; ni++) bf[ni] = sB[cur][(s * 16 + nb0 + ni) * 32 + slB];
#pragma unroll
            for (int mi = 0; mi < 4; mi++)
#pragma unroll
                for (int ni = 0; ni < 4; ni++)
                    mma_tf32(acc[mi][ni], (const uint32_t*)&af[mi], (const uint32_t*)&bf[ni]);
        }

        if (more) {
            int nxt = cur ^ 1;
            float va[8] = {pa0.x,pa0.y,pa0.z,pa0.w,pa1.x,pa1.y,pa1.z,pa1.w};
            float* baseA = (float*)&sA[nxt][(as * 8 + aB) * 32];
#pragma unroll
            for (int kk = 0; kk < 8; kk++)
                baseA[aSlot[kk & 3] * 4 + aRegBase + 2 * (kk >> 2)] = tf32r(va[kk]);
            float vb[8] = {pb0.x,pb0.y,pb0.z,pb0.w,pb1.x,pb1.y,pb1.z,pb1.w};
            if (TRANSB) {
                float2* baseB = &sB[nxt][(as * 16 + aB * 2 + (arr >> 3)) * 32];
#pragma unroll
                for (int kk = 0; kk < 4; kk++)
                    baseB[bSlot[kk]] = make_float2(tf32r(vb[kk]), tf32r(vb[kk + 4]));
            } else {
                int s  = bk_nn >> 3, kk = bk_nn & 7, c = kk & 3, reg = kk >> 2;
                int nb = bn_nn >> 3;
                float* baseB = (float*)&sB[nxt][(s * 16 + nb) * 32];
#pragma unroll
                for (int j = 0; j < 8; j++) {
                    int slot = (j * 4 + c) ^ ((j & 4) >> 1);
                    baseB[slot * 2 + reg] = tf32r(vb[j]);
                }
            }
        }
        __syncthreads();
    }

    int g = lane >> 2, c2 = (lane & 3) * 2;
#pragma unroll
    for (int mi = 0; mi < 4; mi++) {
#pragma unroll
        for (int ni = 0; ni < 4; ni++) {
            int r0 = m0 + wm + mi * 16 + g;
            int cn = n0 + wn + ni * 8 + c2;
#pragma unroll
            for (int e = 0; e < 4; e++) {
                int gm = r0 + (e >= 2 ? 8 : 0);
                int gn = cn + (e & 1);
                if (gm >= M || gn >= N) continue;
                float vv = acc[mi][ni][e] * scale;
                if (bias)   vv += bias[gn];
                if (doGelu) vv = gelu_f(vv);
                if (R)      vv += R[(long)gm * ldc + gn];
                C[(long)gm * ldc + gn] = vv;
            }
        }
    }
}

// ---------------- dedicated logits kernel (M=2, fp32, memory-bound) ----------
__global__ __launch_bounds__(256)
void logits_k(const float* __restrict__ fin,
              const float* __restrict__ Wemb,
              float* __restrict__ out)
{
    __shared__ float f0[Dc], f1[Dc];
    int tid = threadIdx.x;
    for (int i = tid; i < Dc; i += 256) { f0[i] = fin[i]; f1[i] = fin[Dc + i]; }
    __syncthreads();
    int warp = tid >> 5, lane = tid & 31;
    long v = (long)blockIdx.x * 8 + warp;
    if (v >= Vc) return;
    const float* w = Wemb + v * Dc;
    float d0 = 0.f, d1 = 0.f;
    for (int i = lane * 4; i < Dc; i += 128) {
        float4 wv = *(const float4*)(w + i);
        d0 += wv.x * f0[i] + wv.y * f0[i+1] + wv.z * f0[i+2] + wv.w * f0[i+3];
        d1 += wv.x * f1[i] + wv.y * f1[i+1] + wv.z * f1[i+2] + wv.w * f1[i+3];
    }
#pragma unroll
    for (int o = 16; o > 0; o >>= 1) {
        d0 += __shfl_xor_sync(0xffffffff, d0, o);
        d1 += __shfl_xor_sync(0xffffffff, d1, o);
    }
    if (lane == 0) { out[v] = d0; out[(long)Vc + v] = d1; }
}

// ---------------- host-side launch helper ----------------
static inline void launch_nt(const float* A, int lda,
                             const float* B, int ldb,
                             float* C, int ldc,
                             int M, int N, int K,
                             const float* bias, const float* resid,
                             float scale, int gelu)
{
    dim3 g((N + BN - 1) / BN, (M + BM - 1) / BM, 1);
    gemm_tc<true><<<g, 256>>>(A, lda, 0, 0, B, ldb, 0, 0, C, ldc, 0, 0,
                              M, N, K, bias, resid, scale, gelu, 0, 0, 1);
}

#define FLASH_SMEM 65536

extern "C" void kernel_launch(void* const* d_in, const int* in_sizes, int n_in,
                              void* d_out, int out_size)
{
    const int*   x    = (const int*)  d_in[0];
    const float* Wemb = (const float*)d_in[1];
    const float* pos  = (const float*)d_in[2];
    const float* Wq   = (const float*)d_in[3];
    const float* Wk   = (const float*)d_in[4];
    const float* Wv   = (const float*)d_in[5];
    const float* Wo   = (const float*)d_in[6];
    const float* bo   = (const float*)d_in[7];
    const float* n1s  = (const float*)d_in[8];
    const float* n1b  = (const float*)d_in[9];
    const float* n2s  = (const float*)d_in[10];
    const float* n2b  = (const float*)d_in[11];
    const float* W1   = (const float*)d_in[12];
    const float* b1   = (const float*)d_in[13];
    const float* W2   = (const float*)d_in[14];
    const float* b2   = (const float*)d_in[15];
    const float* fs   = (const float*)d_in[16];
    const float* fb   = (const float*)d_in[17];
    float* out = (float*)d_out;

    cudaFuncSetAttribute(flash_k, cudaFuncAttributeMaxDynamicSharedMemorySize, FLASH_SMEM);

    float *h, *xn, *q, *k, *v, *ctx, *ff, *fin;
    cudaGetSymbolAddress((void**)&h,   g_h);
    cudaGetSymbolAddress((void**)&xn,  g_xn);
    cudaGetSymbolAddress((void**)&q,   g_q);
    cudaGetSymbolAddress((void**)&k,   g_k);
    cudaGetSymbolAddress((void**)&v,   g_v);
    cudaGetSymbolAddress((void**)&ctx, g_ctx);
    cudaGetSymbolAddress((void**)&ff,  g_ff);
    cudaGetSymbolAddress((void**)&fin, g_fin);

    const long TD = (long)Tc * Dc;

    {
        long n = (long)BTc * Dc;
        embed_k<<<(unsigned)((n + 255) / 256), 256>>>(x, Wemb, pos, h);
    }

    for (int l = 0; l < Lc; l++) {
        const float* Wql = Wq + (long)l * Dc * Dc;
        const float* Wkl = Wk + (long)l * Dc * Dc;
        const float* Wvl = Wv + (long)l * Dc * Dc;
        const float* Wol = Wo + (long)l * Dc * Dc;
        const float* bol = bo + (long)l * Dc;
        const float* W1l = W1 + (long)l * DFFc * Dc;
        const float* b1l = b1 + (long)l * DFFc;
        const float* W2l = W2 + (long)l * Dc * DFFc;
        const float* b2l = b2 + (long)l * Dc;

        // LN1
        ln_k<<<BTc, 256>>>(h, Dc, xn, Dc, n1s + (long)l * Dc, n1b + (long)l * Dc);

        // Q,K,V = xn @ W^T
        launch_nt(xn, Dc, Wql, Dc, q, Dc, BTc, Dc, Dc, 0, 0, 1.f, 0);
        launch_nt(xn, Dc, Wkl, Dc, k, Dc, BTc, Dc, Dc, 0, 0, 1.f, 0);
        launch_nt(xn, Dc, Wvl, Dc, v, Dc, BTc, Dc, Dc, 0, 0, 1.f, 0);

        // fused causal attention: ctx = softmax(mask(QK^T)/8) @ V
        {
            dim3 fg(Tc / 128, Bc * Hc);
            flash_k<<<fg, 256, FLASH_SMEM>>>(q, k, v, ctx);
        }

        // h = h + ctx @ Wo^T + bo
        launch_nt(ctx, Dc, Wol, Dc, h, Dc, BTc, Dc, Dc, bol, h, 1.f, 0);

        // LN2
        ln_k<<<BTc, 256>>>(h, Dc, xn, Dc, n2s + (long)l * Dc, n2b + (long)l * Dc);

        // ff = gelu(xn @ W1^T + b1)
        launch_nt(xn, Dc, W1l, Dc, ff, DFFc, BTc, DFFc, Dc, b1l, 0, 1.f, 1);

        // h = h + ff @ W2^T + b2
        launch_nt(ff, DFFc, W2l, DFFc, h, Dc, BTc, Dc, DFFc, b2l, h, 1.f, 0);
    }

    // final LN on the 2 last-token rows only
    ln_k<<<Bc, 256>>>(h + (long)(Tc - 1) * Dc, TD, fin, Dc, fs, fb);

    // logits (fp32, memory-bound dedicated kernel)
    logits_k<<<(Vc + 7) / 8, 256>>>(fin, Wemb, out);
}

// round 10
// speedup vs baseline: 1.3940x; 1.3428x over previous
#include <cuda_runtime.h>
#include <cuda_bf16.h>
#include <cuda_fp16.h>
#include <math.h>
#include <stdint.h>

// ---------------- problem constants ----------------
#define Bc   2
#define Tc   2048
#define Dc   1024
#define Hc   16
#define HDc  64
#define DFFc 4096
#define Lc   8
#define Vc   50257
#define BTc  (Bc*Tc)          // 4096
#define EPSc 1e-5f

// ---------------- static device scratch (no allocs allowed) ----------------
__device__ float g_h  [BTc*Dc];
__device__ float g_xn [BTc*Dc];
__device__ float g_q  [BTc*Dc];
__device__ float g_k  [BTc*Dc];
__device__ float g_v  [BTc*Dc];
__device__ float g_ctx[BTc*Dc];
__device__ float g_ff [(long)BTc*DFFc];
__device__ float g_fin[Bc*Dc];               // final-LN of last tokens

// ---------------- helpers ----------------
__device__ __forceinline__ float gelu_f(float x) {
    const float c = 0.7978845608028654f;
    return 0.5f * x * (1.0f + tanhf(c * (x + 0.044715f * x * x * x)));
}
__device__ __forceinline__ float tf32r(float x) {
    uint32_t u;
    asm("cvt.rna.tf32.f32 %0, %1;" : "=r"(u) : "f"(x));
    return __uint_as_float(u);
}
__device__ __forceinline__ void mma_tf32(float* c, const uint32_t* a, const uint32_t* b) {
    asm volatile(
        "mma.sync.aligned.m16n8k8.row.col.f32.tf32.tf32.f32 "
        "{%0,%1,%2,%3}, {%4,%5,%6,%7}, {%8,%9}, {%0,%1,%2,%3};"
        : "+f"(c[0]), "+f"(c[1]), "+f"(c[2]), "+f"(c[3])
        : "r"(a[0]), "r"(a[1]), "r"(a[2]), "r"(a[3]), "r"(b[0]), "r"(b[1]));
}
__device__ __forceinline__ void mma_f16(float* c, const uint32_t* a, const uint32_t* b) {
    asm volatile(
        "mma.sync.aligned.m16n8k16.row.col.f32.f16.f16.f32 "
        "{%0,%1,%2,%3}, {%4,%5,%6,%7}, {%8,%9}, {%0,%1,%2,%3};"
        : "+f"(c[0]), "+f"(c[1]), "+f"(c[2]), "+f"(c[3])
        : "r"(a[0]), "r"(a[1]), "r"(a[2]), "r"(a[3]), "r"(b[0]), "r"(b[1]));
}

// ---------------- embedding ----------------
__global__ void embed_k(const int* __restrict__ x,
                        const float* __restrict__ Wemb,
                        const float* __restrict__ pos,
                        float* __restrict__ h)
{
    long i = (long)blockIdx.x * blockDim.x + threadIdx.x;
    if (i >= (long)BTc * Dc) return;
    int row = (int)(i / Dc);
    int d   = (int)(i % Dc);
    int t   = row % Tc;
    int tok = x[row];
    h[i] = Wemb[(long)tok * Dc + d] + pos[(long)t * Dc + d];
}

// ---------------- layernorm (ddof=1, std+eps) ----------------
__global__ void ln_k(const float* __restrict__ in, long inStride,
                     float* __restrict__ out, long outStride,
                     const float* __restrict__ sc, const float* __restrict__ sh)
{
    __shared__ float red[256];
    int r = blockIdx.x, tid = threadIdx.x;
    const float* x = in + (long)r * inStride;
    float xv[4];
    float s = 0.f;
#pragma unroll
    for (int i = 0; i < 4; i++) { xv[i] = x[tid + i * 256]; s += xv[i]; }
    red[tid] = s; __syncthreads();
    for (int st = 128; st > 0; st >>= 1) { if (tid < st) red[tid] += red[tid + st]; __syncthreads(); }
    float mean = red[0] * (1.0f / (float)Dc);
    __syncthreads();
    float v = 0.f;
#pragma unroll
    for (int i = 0; i < 4; i++) { float t = xv[i] - mean; v += t * t; }
    red[tid] = v; __syncthreads();
    for (int st = 128; st > 0; st >>= 1) { if (tid < st) red[tid] += red[tid + st]; __syncthreads(); }
    float inv = 1.0f / (sqrtf(red[0] / (float)(Dc - 1)) + EPSc);
    float* o = out + (long)r * outStride;
#pragma unroll
    for (int i = 0; i < 4; i++) { int d = tid + i * 256; o[d] = sc[d] * ((xv[i] - mean) * inv) + sh[d]; }
}

// =====================================================================
// flash_k (R9-proven): fused causal attention, q-tile 128 rows, 256 thr.
// =====================================================================
__global__ __launch_bounds__(256)
void flash_k(const float* __restrict__ Qg, const float* __restrict__ Kg,
             const float* __restrict__ Vg, float* __restrict__ Og)
{
    extern __shared__ float4 dsm[];
    float4* Ks = dsm;            // [1024]
    float4* Vs = dsm + 1024;     // [1024]
    float4* Ps = dsm + 2048;     // [2048] (8 warps x 256)
    float*  Qs = (float*)dsm;    // [128*68] transient

    int qt = (int)gridDim.x - 1 - blockIdx.x;
    int q0 = qt * 128;
    int z  = blockIdx.y;
    int b  = z / Hc, hh = z % Hc;
    long base = (long)b * Tc * Dc + (long)hh * HDc;
    const float* Qb = Qg + base;
    const float* Kb = Kg + base;
    const float* Vb = Vg + base;
    float* Ob = Og + base;

    int tid = threadIdx.x, lane = tid & 31, warp = tid >> 5;
    int g = lane >> 2, c = lane & 3;

    {
        int kr = tid >> 1, half = tid & 1;
        const float* src = Qb + (long)(q0 + kr) * Dc + half * 32;
        float* dst = Qs + kr * 68 + half * 32;
#pragma unroll
        for (int f = 0; f < 8; f++)
            *(float4*)(dst + f * 4) = *(const float4*)(src + f * 4);
    }
    __syncthreads();

    uint32_t qf[8][4];
    {
        int r0w = warp * 16 + g;
#pragma unroll
        for (int kb = 0; kb < 8; kb++) {
            int kc = kb * 8 + c;
            qf[kb][0] = __float_as_uint(tf32r(Qs[r0w * 68 + kc]));
            qf[kb][1] = __float_as_uint(tf32r(Qs[(r0w + 8) * 68 + kc]));
            qf[kb][2] = __float_as_uint(tf32r(Qs[r0w * 68 + kc + 4]));
            qf[kb][3] = __float_as_uint(tf32r(Qs[(r0w + 8) * 68 + kc + 4]));
        }
    }
    __syncthreads();

    float oacc[8][4];
#pragma unroll
    for (int i = 0; i < 8; i++)
#pragma unroll
        for (int e = 0; e < 4; e++) oacc[i][e] = 0.f;
    float m0 = -1e30f, m1 = -1e30f, l0 = 0.f, l1 = 0.f;

    bool isK = tid < 128;
    int t = isK ? tid : (tid - 128);
    int jK  = t >> 5;
    int gK  = (t >> 2) & 7;
    int kb2 = t & 3;
    const float* Kp0 = Kb + (long)(16 * jK + gK) * Dc;
    const float* Kp1 = Kp0 + 8L * Dc;
    int vr = t >> 1, vh = t & 1;
    int vkb = vr >> 3, vc8 = vr & 7;
    int vcc = vc8 & 3, vhi = vc8 >> 2;
    int vsw = (vkb >> 1) & 3;

    int nkt = 2 * qt + 2;
    for (int kt = 0; kt < nkt; kt++) {
        int k0 = kt * 64;

        if (isK) {
#pragma unroll
            for (int i = 0; i < 2; i++) {
                int kb = kb2 * 2 + i;
                const float* p0 = Kp0 + (long)k0 * Dc + kb * 8;
                const float* p1 = Kp1 + (long)k0 * Dc + kb * 8;
                float4 a0 = *(const float4*)p0, a1 = *(const float4*)(p0 + 4);
                float4 b0 = *(const float4*)p1, b1 = *(const float4*)(p1 + 4);
                const float* A0 = (const float*)&a0; const float* A1 = (const float*)&a1;
                const float* B0 = (const float*)&b0; const float* B1 = (const float*)&b1;
                int sw = (kb >> 1) & 3;
#pragma unroll
                for (int cc = 0; cc < 4; cc++) {
                    int slot = kb * 128 + jK * 32 + ((cc ^ sw) << 3) + gK;
                    Ks[slot] = make_float4(tf32r(A0[cc]), tf32r(A1[cc]),
                                           tf32r(B0[cc]), tf32r(B1[cc]));
                }
            }
        } else {
            const float* vsrc = Vb + (long)(k0 + vr) * Dc + vh * 32;
            float* vs = (float*)Vs;
#pragma unroll
            for (int f = 0; f < 8; f++) {
                float4 vv = *(const float4*)(vsrc + f * 4);
                const float* V4 = (const float*)&vv;
#pragma unroll
                for (int e = 0; e < 4; e++) {
                    int d  = vh * 32 + f * 4 + e;
                    int jj = d >> 4, g0 = d & 15;
                    int gg = g0 & 7;
                    int comp = vhi + ((g0 >> 3) << 1);
                    int slot = vkb * 128 + jj * 32 + ((vcc ^ vsw) << 3) + gg;
                    vs[slot * 4 + comp] = tf32r(V4[e]);
                }
            }
        }
        __syncthreads();

        bool active = (k0 <= q0 + warp * 16 + 15);
        if (active) {
            float sacc[8][4];
#pragma unroll
            for (int i = 0; i < 8; i++)
#pragma unroll
                for (int e = 0; e < 4; e++) sacc[i][e] = 0.f;
#pragma unroll
            for (int kb = 0; kb < 8; kb++) {
                int sw = (kb >> 1) & 3;
                int fb = kb * 128 + ((c ^ sw) << 3) + g;
                float4 bq0 = Ks[fb];
                float4 bq1 = Ks[fb + 32];
                float4 bq2 = Ks[fb + 64];
                float4 bq3 = Ks[fb + 96];
                mma_tf32(sacc[0], qf[kb], (const uint32_t*)&bq0.x);
                mma_tf32(sacc[1], qf[kb], (const uint32_t*)&bq0.z);
                mma_tf32(sacc[2], qf[kb], (const uint32_t*)&bq1.x);
                mma_tf32(sacc[3], qf[kb], (const uint32_t*)&bq1.z);
                mma_tf32(sacc[4], qf[kb], (const uint32_t*)&bq2.x);
                mma_tf32(sacc[5], qf[kb], (const uint32_t*)&bq2.z);
                mma_tf32(sacc[6], qf[kb], (const uint32_t*)&bq3.x);
                mma_tf32(sacc[7], qf[kb], (const uint32_t*)&bq3.z);
            }

            int qr0 = q0 + warp * 16 + g;
            int qr1 = qr0 + 8;
            bool maskNeed = (k0 + 63 > q0 + warp * 16);
            float rm0 = -1e30f, rm1 = -1e30f;
#pragma unroll
            for (int ni = 0; ni < 8; ni++) {
#pragma unroll
                for (int e = 0; e < 4; e++) {
                    float vvv = sacc[ni][e] * 0.125f;
                    if (maskNeed) {
                        int kc = k0 + ni * 8 + c * 2 + (e & 1);
                        if (kc > ((e >= 2) ? qr1 : qr0)) vvv = -1e30f;
                    }
                    sacc[ni][e] = vvv;
                    if (e < 2) rm0 = fmaxf(rm0, vvv); else rm1 = fmaxf(rm1, vvv);
                }
            }
            rm0 = fmaxf(rm0, __shfl_xor_sync(0xffffffffu, rm0, 1));
            rm0 = fmaxf(rm0, __shfl_xor_sync(0xffffffffu, rm0, 2));
            rm1 = fmaxf(rm1, __shfl_xor_sync(0xffffffffu, rm1, 1));
            rm1 = fmaxf(rm1, __shfl_xor_sync(0xffffffffu, rm1, 2));
            float mn0 = fmaxf(m0, rm0), mn1 = fmaxf(m1, rm1);
            float sc0 = __expf(m0 - mn0), sc1 = __expf(m1 - mn1);
            float rs0 = 0.f, rs1 = 0.f;
#pragma unroll
            for (int ni = 0; ni < 8; ni++) {
#pragma unroll
                for (int e = 0; e < 4; e++) {
                    float ee = __expf(sacc[ni][e] - ((e < 2) ? mn0 : mn1));
                    sacc[ni][e] = ee;
                    if (e < 2) rs0 += ee; else rs1 += ee;
                }
            }
            rs0 += __shfl_xor_sync(0xffffffffu, rs0, 1);
            rs0 += __shfl_xor_sync(0xffffffffu, rs0, 2);
            rs1 += __shfl_xor_sync(0xffffffffu, rs1, 1);
            rs1 += __shfl_xor_sync(0xffffffffu, rs1, 2);
            l0 = l0 * sc0 + rs0;
            l1 = l1 * sc1 + rs1;
            m0 = mn0; m1 = mn1;
#pragma unroll
            for (int ni = 0; ni < 8; ni++) {
#pragma unroll
                for (int e = 0; e < 4; e++) oacc[ni][e] *= (e < 2) ? sc0 : sc1;
            }

            {
                float* ps = (float*)(Ps + warp * 256);
                int c8a = 2 * c;
                int ccA = c8a & 3, hiA = c8a >> 2;
                int c8b = c8a + 1;
                int ccB = c8b & 3, hiB = c8b >> 2;
#pragma unroll
                for (int ni = 0; ni < 8; ni++) {
                    int slotA = ni * 32 + ccA * 8 + g;
                    *(float2*)(ps + slotA * 4 + hiA * 2) =
                        make_float2(tf32r(sacc[ni][0]), tf32r(sacc[ni][2]));
                    int slotB = ni * 32 + ccB * 8 + g;
                    *(float2*)(ps + slotB * 4 + hiB * 2) =
                        make_float2(tf32r(sacc[ni][1]), tf32r(sacc[ni][3]));
                }
            }
            __syncwarp();

#pragma unroll
            for (int kb = 0; kb < 8; kb++) {
                float4 pf = Ps[warp * 256 + kb * 32 + c * 8 + g];
                int sw = (kb >> 1) & 3;
                int fb = kb * 128 + ((c ^ sw) << 3) + g;
                float4 bv0 = Vs[fb];
                float4 bv1 = Vs[fb + 32];
                float4 bv2 = Vs[fb + 64];
                float4 bv3 = Vs[fb + 96];
                mma_tf32(oacc[0], (const uint32_t*)&pf, (const uint32_t*)&bv0.x);
                mma_tf32(oacc[1], (const uint32_t*)&pf, (const uint32_t*)&bv0.z);
                mma_tf32(oacc[2], (const uint32_t*)&pf, (const uint32_t*)&bv1.x);
                mma_tf32(oacc[3], (const uint32_t*)&pf, (const uint32_t*)&bv1.z);
                mma_tf32(oacc[4], (const uint32_t*)&pf, (const uint32_t*)&bv2.x);
                mma_tf32(oacc[5], (const uint32_t*)&pf, (const uint32_t*)&bv2.z);
                mma_tf32(oacc[6], (const uint32_t*)&pf, (const uint32_t*)&bv3.x);
                mma_tf32(oacc[7], (const uint32_t*)&pf, (const uint32_t*)&bv3.z);
            }
        }
        __syncthreads();
    }

    float il0 = 1.f / l0, il1 = 1.f / l1;
    int r0 = q0 + warp * 16 + g;
#pragma unroll
    for (int ni = 0; ni < 8; ni++) {
        int d = ni * 8 + 2 * c;
        *(float2*)(Ob + (long)r0 * Dc + d) =
            make_float2(oacc[ni][0] * il0, oacc[ni][1] * il0);
        *(float2*)(Ob + (long)(r0 + 8) * Dc + d) =
            make_float2(oacc[ni][2] * il1, oacc[ni][3] * il1);
    }
}

// =====================================================================
// gemm_f16: dense NT GEMM on fp16 tensor cores (m16n8k16, fp32 accum).
// 128x128 block, 8 warps of 64x32 tiles, BK=16, double-buffered.
// Requires M,N multiples of 128, K multiple of 16.
// C = A[M,K] @ B[N,K]^T [+bias][gelu][+resid]
// Fragment-slot smem: entry e = 4g+c, phys = e ^ ((e>>3)&3) (B also ^ (nb&1)<<3)
// A slot = uint4 {a0,a1,a2,a3}; B slot = uint2 {b0,b1}.
// =====================================================================
#define BM 128
#define BN 128
#define BKH 16

__global__ __launch_bounds__(256, 2)
void gemm_f16(const float* __restrict__ A, int lda,
              const float* __restrict__ B, int ldb,
              float* __restrict__ C, int ldc, int K,
              const float* __restrict__ bias,
              const float* __restrict__ resid, int doGelu)
{
    __shared__ uint32_t sAx[2][8][128];    // [stage][mblock][32 slots * 4 words]
    __shared__ uint32_t sBx[2][16][64];    // [stage][nblock][32 slots * 2 words]

    int m0 = blockIdx.y * BM, n0 = blockIdx.x * BN;
    int tid = threadIdx.x, lane = tid & 31, warp = tid >> 5;
    int wm = (warp & 1) * 64, wn = (warp >> 1) * 32;
    int bA0 = wm >> 4, nb0 = wn >> 3;

    float acc[4][4][4];
#pragma unroll
    for (int i = 0; i < 4; i++)
#pragma unroll
        for (int jx = 0; jx < 4; jx++)
#pragma unroll
            for (int e = 0; e < 4; e++) acc[i][jx][e] = 0.f;

    // staging role
    int r  = tid >> 1, hf = tid & 1;
    int j  = r >> 4, nb = r >> 3, g = r & 7, hi = (r >> 3) & 1;
    int swzA = (g >> 1) & 3;
    int nbx  = (nb & 1) << 3;
    const float* Ap = A + (long)(m0 + r) * lda + hf * 8;
    const float* Bp = B + (long)(n0 + r) * ldb + hf * 8;

    int nIter = K / BKH;

    float4 pa0, pa1, pb0, pb1;
    pa0 = *(const float4*)(Ap);     pa1 = *(const float4*)(Ap + 4);
    pb0 = *(const float4*)(Bp);     pb1 = *(const float4*)(Bp + 4);

    // stage chunk 0
    {
        float va[8] = {pa0.x,pa0.y,pa0.z,pa0.w,pa1.x,pa1.y,pa1.z,pa1.w};
        float vb[8] = {pb0.x,pb0.y,pb0.z,pb0.w,pb1.x,pb1.y,pb1.z,pb1.w};
        uint32_t* aw = sAx[0][j];
        uint32_t* bw = sBx[0][nb];
#pragma unroll
        for (int c = 0; c < 4; c++) {
            __half2 ha = __floats2half2_rn(va[2*c], va[2*c+1]);
            __half2 hb = __floats2half2_rn(vb[2*c], vb[2*c+1]);
            int ph = (4 * g + c) ^ swzA;
            aw[ph * 4 + hi + 2 * hf] = *(uint32_t*)&ha;
            bw[(ph ^ nbx) * 2 + hf]  = *(uint32_t*)&hb;
        }
    }
    __syncthreads();

    int physC = lane ^ ((lane >> 3) & 3);

    for (int it = 0; it < nIter; it++) {
        int cur = it & 1;
        bool more = (it + 1) < nIter;
        if (more) {
            long ko = (long)(it + 1) * BKH;
            pa0 = *(const float4*)(Ap + ko); pa1 = *(const float4*)(Ap + ko + 4);
            pb0 = *(const float4*)(Bp + ko); pb1 = *(const float4*)(Bp + ko + 4);
        }

        // ---- mma ----
        {
            float4 af[4]; float2 bf[4];
#pragma unroll
            for (int mi = 0; mi < 4; mi++)
                af[mi] = ((const float4*)sAx[cur][bA0 + mi])[physC];
#pragma unroll
            for (int ni = 0; ni < 4; ni++) {
                int nb2 = nb0 + ni;
                bf[ni] = ((const float2*)sBx[cur][nb2])[physC ^ ((nb2 & 1) << 3)];
            }
#pragma unroll
            for (int mi = 0; mi < 4; mi++)
#pragma unroll
                for (int ni = 0; ni < 4; ni++)
                    mma_f16(acc[mi][ni], (const uint32_t*)&af[mi], (const uint32_t*)&bf[ni]);
        }

        if (more) {
            int nxt = cur ^ 1;
            float va[8] = {pa0.x,pa0.y,pa0.z,pa0.w,pa1.x,pa1.y,pa1.z,pa1.w};
            float vb[8] = {pb0.x,pb0.y,pb0.z,pb0.w,pb1.x,pb1.y,pb1.z,pb1.w};
            uint32_t* aw = sAx[nxt][j];
            uint32_t* bw = sBx[nxt][nb];
#pragma unroll
            for (int c = 0; c < 4; c++) {
                __half2 ha = __floats2half2_rn(va[2*c], va[2*c+1]);
                __half2 hb = __floats2half2_rn(vb[2*c], vb[2*c+1]);
                int ph = (4 * g + c) ^ swzA;
                aw[ph * 4 + hi + 2 * hf] = *(uint32_t*)&ha;
                bw[(ph ^ nbx) * 2 + hf]  = *(uint32_t*)&hb;
            }
        }
        __syncthreads();
    }

    // ---- epilogue (no bounds checks: M,N multiples of 128) ----
    int ge = lane >> 2, c2 = (lane & 3) * 2;
#pragma unroll
    for (int mi = 0; mi < 4; mi++) {
#pragma unroll
        for (int ni = 0; ni < 4; ni++) {
            int gm = m0 + wm + mi * 16 + ge;
            int gn = n0 + wn + ni * 8 + c2;
            float v0 = acc[mi][ni][0], v1 = acc[mi][ni][1];
            float v2 = acc[mi][ni][2], v3 = acc[mi][ni][3];
            if (bias) {
                float b0 = bias[gn], b1 = bias[gn + 1];
                v0 += b0; v1 += b1; v2 += b0; v3 += b1;
            }
            if (doGelu) { v0 = gelu_f(v0); v1 = gelu_f(v1); v2 = gelu_f(v2); v3 = gelu_f(v3); }
            if (resid) {
                const float* r0p = resid + (long)gm * ldc + gn;
                const float* r1p = resid + (long)(gm + 8) * ldc + gn;
                v0 += r0p[0]; v1 += r0p[1]; v2 += r1p[0]; v3 += r1p[1];
            }
            *(float2*)(C + (long)gm * ldc + gn)       = make_float2(v0, v1);
            *(float2*)(C + (long)(gm + 8) * ldc + gn) = make_float2(v2, v3);
        }
    }
}

// ---------------- dedicated logits kernel (M=2, fp32, memory-bound) ----------
__global__ __launch_bounds__(256)
void logits_k(const float* __restrict__ fin,
              const float* __restrict__ Wemb,
              float* __restrict__ out)
{
    __shared__ float f0[Dc], f1[Dc];
    int tid = threadIdx.x;
    for (int i = tid; i < Dc; i += 256) { f0[i] = fin[i]; f1[i] = fin[Dc + i]; }
    __syncthreads();
    int warp = tid >> 5, lane = tid & 31;
    long v = (long)blockIdx.x * 8 + warp;
    if (v >= Vc) return;
    const float* w = Wemb + v * Dc;
    float d0 = 0.f, d1 = 0.f;
    for (int i = lane * 4; i < Dc; i += 128) {
        float4 wv = *(const float4*)(w + i);
        d0 += wv.x * f0[i] + wv.y * f0[i+1] + wv.z * f0[i+2] + wv.w * f0[i+3];
        d1 += wv.x * f1[i] + wv.y * f1[i+1] + wv.z * f1[i+2] + wv.w * f1[i+3];
    }
#pragma unroll
    for (int o = 16; o > 0; o >>= 1) {
        d0 += __shfl_xor_sync(0xffffffff, d0, o);
        d1 += __shfl_xor_sync(0xffffffff, d1, o);
    }
    if (lane == 0) { out[v] = d0; out[(long)Vc + v] = d1; }
}

// ---------------- host-side launch helper ----------------
static inline void launch_f16(const float* A, int lda,
                              const float* B, int ldb,
                              float* C, int ldc,
                              int M, int N, int K,
                              const float* bias, const float* resid, int gelu)
{
    dim3 g(N / BN, M / BM, 1);
    gemm_f16<<<g, 256>>>(A, lda, B, ldb, C, ldc, K, bias, resid, gelu);
}

#define FLASH_SMEM 65536

extern "C" void kernel_launch(void* const* d_in, const int* in_sizes, int n_in,
                              void* d_out, int out_size)
{
    const int*   x    = (const int*)  d_in[0];
    const float* Wemb = (const float*)d_in[1];
    const float* pos  = (const float*)d_in[2];
    const float* Wq   = (const float*)d_in[3];
    const float* Wk   = (const float*)d_in[4];
    const float* Wv   = (const float*)d_in[5];
    const float* Wo   = (const float*)d_in[6];
    const float* bo   = (const float*)d_in[7];
    const float* n1s  = (const float*)d_in[8];
    const float* n1b  = (const float*)d_in[9];
    const float* n2s  = (const float*)d_in[10];
    const float* n2b  = (const float*)d_in[11];
    const float* W1   = (const float*)d_in[12];
    const float* b1   = (const float*)d_in[13];
    const float* W2   = (const float*)d_in[14];
    const float* b2   = (const float*)d_in[15];
    const float* fs   = (const float*)d_in[16];
    const float* fb   = (const float*)d_in[17];
    float* out = (float*)d_out;

    cudaFuncSetAttribute(flash_k, cudaFuncAttributeMaxDynamicSharedMemorySize, FLASH_SMEM);

    float *h, *xn, *q, *k, *v, *ctx, *ff, *fin;
    cudaGetSymbolAddress((void**)&h,   g_h);
    cudaGetSymbolAddress((void**)&xn,  g_xn);
    cudaGetSymbolAddress((void**)&q,   g_q);
    cudaGetSymbolAddress((void**)&k,   g_k);
    cudaGetSymbolAddress((void**)&v,   g_v);
    cudaGetSymbolAddress((void**)&ctx, g_ctx);
    cudaGetSymbolAddress((void**)&ff,  g_ff);
    cudaGetSymbolAddress((void**)&fin, g_fin);

    const long TD = (long)Tc * Dc;

    {
        long n = (long)BTc * Dc;
        embed_k<<<(unsigned)((n + 255) / 256), 256>>>(x, Wemb, pos, h);
    }

    for (int l = 0; l < Lc; l++) {
        const float* Wql = Wq + (long)l * Dc * Dc;
        const float* Wkl = Wk + (long)l * Dc * Dc;
        const float* Wvl = Wv + (long)l * Dc * Dc;
        const float* Wol = Wo + (long)l * Dc * Dc;
        const float* bol = bo + (long)l * Dc;
        const float* W1l = W1 + (long)l * DFFc * Dc;
        const float* b1l = b1 + (long)l * DFFc;
        const float* W2l = W2 + (long)l * Dc * DFFc;
        const float* b2l = b2 + (long)l * Dc;

        // LN1
        ln_k<<<BTc, 256>>>(h, Dc, xn, Dc, n1s + (long)l * Dc, n1b + (long)l * Dc);

        // Q,K,V = xn @ W^T  (fp16 tensor cores)
        launch_f16(xn, Dc, Wql, Dc, q, Dc, BTc, Dc, Dc, 0, 0, 0);
        launch_f16(xn, Dc, Wkl, Dc, k, Dc, BTc, Dc, Dc, 0, 0, 0);
        launch_f16(xn, Dc, Wvl, Dc, v, Dc, BTc, Dc, Dc, 0, 0, 0);

        // fused causal attention
        {
            dim3 fg(Tc / 128, Bc * Hc);
            flash_k<<<fg, 256, FLASH_SMEM>>>(q, k, v, ctx);
        }

        // h = h + ctx @ Wo^T + bo
        launch_f16(ctx, Dc, Wol, Dc, h, Dc, BTc, Dc, Dc, bol, h, 0);

        // LN2
        ln_k<<<BTc, 256>>>(h, Dc, xn, Dc, n2s + (long)l * Dc, n2b + (long)l * Dc);

        // ff = gelu(xn @ W1^T + b1)
        launch_f16(xn, Dc, W1l, Dc, ff, DFFc, BTc, DFFc, Dc, b1l, 0, 1);

        // h = h + ff @ W2^T + b2
        launch_f16(ff, DFFc, W2l, DFFc, h, Dc, BTc, Dc, DFFc, b2l, h, 0);
    }

    // final LN on the 2 last-token rows only
    ln_k<<<Bc, 256>>>(h + (long)(Tc - 1) * Dc, TD, fin, Dc, fs, fb);

    // logits (fp32, memory-bound dedicated kernel)
    logits_k<<<(Vc + 7) / 8, 256>>>(fin, Wemb, out);
}

// round 11
// speedup vs baseline: 2.0533x; 1.4729x over previous
#include <cuda_runtime.h>
#include <cuda_bf16.h>
#include <cuda_fp16.h>
#include <math.h>
#include <stdint.h>

// ---------------- problem constants ----------------
#define Bc   2
#define Tc   2048
#define Dc   1024
#define Hc   16
#define HDc  64
#define DFFc 4096
#define Lc   8
#define Vc   50257
#define BTc  (Bc*Tc)          // 4096
#define EPSc 1e-5f

// ---------------- static device scratch (no allocs allowed) ----------------
__device__ float g_h  [BTc*Dc];
__device__ float g_xn [BTc*Dc];
__device__ float g_q  [BTc*Dc];
__device__ float g_k  [BTc*Dc];
__device__ float g_v  [BTc*Dc];
__device__ float g_ctx[BTc*Dc];
__device__ float g_ff [(long)BTc*DFFc];
__device__ float g_fin[Bc*Dc];               // final-LN of last tokens

// ---------------- helpers ----------------
__device__ __forceinline__ float gelu_f(float x) {
    const float c = 0.7978845608028654f;
    return 0.5f * x * (1.0f + tanhf(c * (x + 0.044715f * x * x * x)));
}
__device__ __forceinline__ void mma_f16(float* c, const uint32_t* a, const uint32_t* b) {
    asm volatile(
        "mma.sync.aligned.m16n8k16.row.col.f32.f16.f16.f32 "
        "{%0,%1,%2,%3}, {%4,%5,%6,%7}, {%8,%9}, {%0,%1,%2,%3};"
        : "+f"(c[0]), "+f"(c[1]), "+f"(c[2]), "+f"(c[3])
        : "r"(a[0]), "r"(a[1]), "r"(a[2]), "r"(a[3]), "r"(b[0]), "r"(b[1]));
}
__device__ __forceinline__ uint32_t h2pack(float a, float b) {
    __half2 h = __floats2half2_rn(a, b);
    return *(uint32_t*)&h;
}

// ---------------- embedding ----------------
__global__ void embed_k(const int* __restrict__ x,
                        const float* __restrict__ Wemb,
                        const float* __restrict__ pos,
                        float* __restrict__ h)
{
    long i = (long)blockIdx.x * blockDim.x + threadIdx.x;
    if (i >= (long)BTc * Dc) return;
    int row = (int)(i / Dc);
    int d   = (int)(i % Dc);
    int t   = row % Tc;
    int tok = x[row];
    h[i] = Wemb[(long)tok * Dc + d] + pos[(long)t * Dc + d];
}

// ---------------- layernorm (ddof=1, std+eps) ----------------
__global__ void ln_k(const float* __restrict__ in, long inStride,
                     float* __restrict__ out, long outStride,
                     const float* __restrict__ sc, const float* __restrict__ sh)
{
    __shared__ float red[256];
    int r = blockIdx.x, tid = threadIdx.x;
    const float* x = in + (long)r * inStride;
    float xv[4];
    float s = 0.f;
#pragma unroll
    for (int i = 0; i < 4; i++) { xv[i] = x[tid + i * 256]; s += xv[i]; }
    red[tid] = s; __syncthreads();
    for (int st = 128; st > 0; st >>= 1) { if (tid < st) red[tid] += red[tid + st]; __syncthreads(); }
    float mean = red[0] * (1.0f / (float)Dc);
    __syncthreads();
    float v = 0.f;
#pragma unroll
    for (int i = 0; i < 4; i++) { float t = xv[i] - mean; v += t * t; }
    red[tid] = v; __syncthreads();
    for (int st = 128; st > 0; st >>= 1) { if (tid < st) red[tid] += red[tid + st]; __syncthreads(); }
    float inv = 1.0f / (sqrtf(red[0] / (float)(Dc - 1)) + EPSc);
    float* o = out + (long)r * outStride;
#pragma unroll
    for (int i = 0; i < 4; i++) { int d = tid + i * 256; o[d] = sc[d] * ((xv[i] - mean) * inv) + sh[d]; }
}

// =====================================================================
// flash_k v3 (fp16 mma): fused causal attention, q-tile 128 rows, 256 thr.
// 8 warps x 16 q-rows; k-tiles of 64. m16n8k16: P reused register-direct
// (S D-fragment == P A-fragment), K/V staged in gemm_f16 B-slot layout.
// smem: Q transient 34.8KB; K 8KB + V 8KB after Q consumed.
// =====================================================================
__global__ __launch_bounds__(256)
void flash_k(const float* __restrict__ Qg, const float* __restrict__ Kg,
             const float* __restrict__ Vg, float* __restrict__ Og)
{
    __shared__ float fsm[128 * 68];          // 34816 B
    uint32_t* sKf = (uint32_t*)fsm;          // [4][8][64] = 8KB
    uint32_t* sVf = sKf + 2048;              // [4][8][64] = 8KB

    int qt = (int)gridDim.x - 1 - blockIdx.x;   // reversed: long CTAs first
    int q0 = qt * 128;
    int z  = blockIdx.y;
    int b  = z / Hc, hh = z % Hc;
    long base = (long)b * Tc * Dc + (long)hh * HDc;
    const float* Qb = Qg + base;
    const float* Kb = Kg + base;
    const float* Vb = Vg + base;
    float* Ob = Og + base;

    int tid = threadIdx.x, lane = tid & 31, warp = tid >> 5;
    int g = lane >> 2, c = lane & 3;
    int physC = lane ^ ((lane >> 3) & 3);

    // ---- load Q tile (128 x 64) into smem, stride 68 ----
    {
        int kr = tid >> 1, half = tid & 1;
        const float* src = Qb + (long)(q0 + kr) * Dc + half * 32;
        float* dst = fsm + kr * 68 + half * 32;
#pragma unroll
        for (int f = 0; f < 8; f++)
            *(float4*)(dst + f * 4) = *(const float4*)(src + f * 4);
    }
    __syncthreads();

    // ---- Q fragments (fp16, gemm_f16 A order) ----
    uint32_t qf[4][4];
    {
        int r0w = warp * 16 + g;
#pragma unroll
        for (int kb = 0; kb < 4; kb++) {
            int kq = kb * 16 + 2 * c;
            qf[kb][0] = h2pack(fsm[r0w * 68 + kq],           fsm[r0w * 68 + kq + 1]);
            qf[kb][1] = h2pack(fsm[(r0w + 8) * 68 + kq],     fsm[(r0w + 8) * 68 + kq + 1]);
            qf[kb][2] = h2pack(fsm[r0w * 68 + kq + 8],       fsm[r0w * 68 + kq + 9]);
            qf[kb][3] = h2pack(fsm[(r0w + 8) * 68 + kq + 8], fsm[(r0w + 8) * 68 + kq + 9]);
        }
    }
    __syncthreads();   // Q area about to be reused for K/V

    float oacc[8][4];
#pragma unroll
    for (int i = 0; i < 8; i++)
#pragma unroll
        for (int e = 0; e < 4; e++) oacc[i][e] = 0.f;
    float m0 = -1e30f, m1 = -1e30f, l0 = 0.f, l1 = 0.f;

    // staging roles
    bool isK = tid < 128;
    int t = isK ? tid : (tid - 128);
    // K role: n-row = t&63, k-quarter (32 cols) = t>>6 -> kb pair
    int nK  = t & 63;
    int kqK = t >> 6;                 // 0..1 -> kb = 2*kqK + {0,1}
    int nbK = nK >> 3, gK = nK & 7;
    int swzK = (gK >> 1) & 3;
    int nbxK = (nbK & 1) << 3;
    const float* KpBase = Kb + (long)nK * Dc + kqK * 32;
    // V role: k-row = t&63, col-half = t>>6
    int kV = t & 63;
    int chV = t >> 6;
    int kbV = kV >> 4, kkV = kV & 15;
    int cV  = (kkV & 7) >> 1, hfV = (kkV >> 3) & 1, loV = kkV & 1;
    const float* VpBase = Vb + (long)kV * Dc + chV * 32;

    int nkt = 2 * qt + 2;
    for (int kt = 0; kt < nkt; kt++) {
        int k0 = kt * 64;

        if (isK) {
            // stage K rows: kb = 2*kqK + i, 16 floats each
            const float* src = KpBase + (long)k0 * Dc;
#pragma unroll
            for (int i = 0; i < 2; i++) {
                int kb = 2 * kqK + i;
                float4 v0 = *(const float4*)(src + i * 16);
                float4 v1 = *(const float4*)(src + i * 16 + 4);
                float4 v2 = *(const float4*)(src + i * 16 + 8);
                float4 v3 = *(const float4*)(src + i * 16 + 12);
                float vv[16] = {v0.x,v0.y,v0.z,v0.w, v1.x,v1.y,v1.z,v1.w,
                                v2.x,v2.y,v2.z,v2.w, v3.x,v3.y,v3.z,v3.w};
                uint32_t* dst = sKf + kb * 512 + nbK * 64;
#pragma unroll
                for (int cc = 0; cc < 4; cc++) {
                    int s = ((4 * gK + cc) ^ swzK) ^ nbxK;
                    dst[s * 2 + 0] = h2pack(vv[2 * cc],     vv[2 * cc + 1]);
                    dst[s * 2 + 1] = h2pack(vv[8 + 2 * cc], vv[8 + 2 * cc + 1]);
                }
            }
        } else {
            // stage V row kV, 32 cols, transposed into B-slots (half writes)
            const float* src = VpBase + (long)k0 * Dc;
            uint32_t* dstK = sVf + kbV * 512;
#pragma unroll
            for (int f = 0; f < 8; f++) {
                float4 vv = *(const float4*)(src + f * 4);
                const float* V4 = (const float*)&vv;
#pragma unroll
                for (int e = 0; e < 4; e++) {
                    int n  = chV * 32 + f * 4 + e;
                    int nb = n >> 3, gg = n & 7;
                    int s  = ((4 * gg + cV) ^ ((gg >> 1) & 3)) ^ ((nb & 1) << 3);
                    __half* hp = (__half*)&dstK[nb * 64 + s * 2 + hfV];
                    hp[loV] = __float2half_rn(V4[e]);
                }
            }
        }
        __syncthreads();

        // skip tiles entirely above this warp's diagonal
        bool active = (k0 <= q0 + warp * 16 + 15);
        if (active) {
            // ---- S = Q @ K^T (fp16) ----
            float sacc[8][4];
#pragma unroll
            for (int i = 0; i < 8; i++)
#pragma unroll
                for (int e = 0; e < 4; e++) sacc[i][e] = 0.f;
#pragma unroll
            for (int kb = 0; kb < 4; kb++) {
#pragma unroll
                for (int nb = 0; nb < 8; nb++) {
                    uint2 bk = *(uint2*)&sKf[kb * 512 + nb * 64 +
                                             (physC ^ ((nb & 1) << 3)) * 2];
                    mma_f16(sacc[nb], qf[kb], &bk.x);
                }
            }

            // ---- mask, scale, online softmax (unchanged layout) ----
            int qr0 = q0 + warp * 16 + g;
            int qr1 = qr0 + 8;
            bool maskNeed = (k0 + 63 > q0 + warp * 16);
            float rm0 = -1e30f, rm1 = -1e30f;
#pragma unroll
            for (int ni = 0; ni < 8; ni++) {
#pragma unroll
                for (int e = 0; e < 4; e++) {
                    float vvv = sacc[ni][e] * 0.125f;
                    if (maskNeed) {
                        int kc = k0 + ni * 8 + c * 2 + (e & 1);
                        if (kc > ((e >= 2) ? qr1 : qr0)) vvv = -1e30f;
                    }
                    sacc[ni][e] = vvv;
                    if (e < 2) rm0 = fmaxf(rm0, vvv); else rm1 = fmaxf(rm1, vvv);
                }
            }
            rm0 = fmaxf(rm0, __shfl_xor_sync(0xffffffffu, rm0, 1));
            rm0 = fmaxf(rm0, __shfl_xor_sync(0xffffffffu, rm0, 2));
            rm1 = fmaxf(rm1, __shfl_xor_sync(0xffffffffu, rm1, 1));
            rm1 = fmaxf(rm1, __shfl_xor_sync(0xffffffffu, rm1, 2));
            float mn0 = fmaxf(m0, rm0), mn1 = fmaxf(m1, rm1);
            float sc0 = __expf(m0 - mn0), sc1 = __expf(m1 - mn1);
            float rs0 = 0.f, rs1 = 0.f;
#pragma unroll
            for (int ni = 0; ni < 8; ni++) {
#pragma unroll
                for (int e = 0; e < 4; e++) {
                    float ee = __expf(sacc[ni][e] - ((e < 2) ? mn0 : mn1));
                    sacc[ni][e] = ee;
                    if (e < 2) rs0 += ee; else rs1 += ee;
                }
            }
            rs0 += __shfl_xor_sync(0xffffffffu, rs0, 1);
            rs0 += __shfl_xor_sync(0xffffffffu, rs0, 2);
            rs1 += __shfl_xor_sync(0xffffffffu, rs1, 1);
            rs1 += __shfl_xor_sync(0xffffffffu, rs1, 2);
            l0 = l0 * sc0 + rs0;
            l1 = l1 * sc1 + rs1;
            m0 = mn0; m1 = mn1;
#pragma unroll
            for (int ni = 0; ni < 8; ni++) {
#pragma unroll
                for (int e = 0; e < 4; e++) oacc[ni][e] *= (e < 2) ? sc0 : sc1;
            }

            // ---- P: register-direct A-fragments (S D-frag == P A-frag) ----
            // ---- O += P @ V (fp16) ----
#pragma unroll
            for (int kb = 0; kb < 4; kb++) {
                uint32_t pf[4];
                pf[0] = h2pack(sacc[2 * kb][0],     sacc[2 * kb][1]);
                pf[1] = h2pack(sacc[2 * kb][2],     sacc[2 * kb][3]);
                pf[2] = h2pack(sacc[2 * kb + 1][0], sacc[2 * kb + 1][1]);
                pf[3] = h2pack(sacc[2 * kb + 1][2], sacc[2 * kb + 1][3]);
#pragma unroll
                for (int nb = 0; nb < 8; nb++) {
                    uint2 bv = *(uint2*)&sVf[kb * 512 + nb * 64 +
                                             (physC ^ ((nb & 1) << 3)) * 2];
                    mma_f16(oacc[nb], pf, &bv.x);
                }
            }
        }
        __syncthreads();   // all reads of K/V done before next staging
    }

    // ---- normalize + write ctx ----
    float il0 = 1.f / l0, il1 = 1.f / l1;
    int r0 = q0 + warp * 16 + g;
#pragma unroll
    for (int ni = 0; ni < 8; ni++) {
        int d = ni * 8 + 2 * c;
        *(float2*)(Ob + (long)r0 * Dc + d) =
            make_float2(oacc[ni][0] * il0, oacc[ni][1] * il0);
        *(float2*)(Ob + (long)(r0 + 8) * Dc + d) =
            make_float2(oacc[ni][2] * il1, oacc[ni][3] * il1);
    }
}

// =====================================================================
// gemm_f16 (R10-proven): dense NT GEMM on fp16 tensor cores.
// =====================================================================
#define BM 128
#define BN 128
#define BKH 16

__global__ __launch_bounds__(256, 2)
void gemm_f16(const float* __restrict__ A, int lda,
              const float* __restrict__ B, int ldb,
              float* __restrict__ C, int ldc, int K,
              const float* __restrict__ bias,
              const float* __restrict__ resid, int doGelu)
{
    __shared__ uint32_t sAx[2][8][128];
    __shared__ uint32_t sBx[2][16][64];

    int m0 = blockIdx.y * BM, n0 = blockIdx.x * BN;
    int tid = threadIdx.x, lane = tid & 31, warp = tid >> 5;
    int wm = (warp & 1) * 64, wn = (warp >> 1) * 32;
    int bA0 = wm >> 4, nb0 = wn >> 3;

    float acc[4][4][4];
#pragma unroll
    for (int i = 0; i < 4; i++)
#pragma unroll
        for (int jx = 0; jx < 4; jx++)
#pragma unroll
            for (int e = 0; e < 4; e++) acc[i][jx][e] = 0.f;

    int r  = tid >> 1, hf = tid & 1;
    int j  = r >> 4, nb = r >> 3, g = r & 7, hi = (r >> 3) & 1;
    int swzA = (g >> 1) & 3;
    int nbx  = (nb & 1) << 3;
    const float* Ap = A + (long)(m0 + r) * lda + hf * 8;
    const float* Bp = B + (long)(n0 + r) * ldb + hf * 8;

    int nIter = K / BKH;

    float4 pa0, pa1, pb0, pb1;
    pa0 = *(const float4*)(Ap);     pa1 = *(const float4*)(Ap + 4);
    pb0 = *(const float4*)(Bp);     pb1 = *(const float4*)(Bp + 4);

    {
        float va[8] = {pa0.x,pa0.y,pa0.z,pa0.w,pa1.x,pa1.y,pa1.z,pa1.w};
        float vb[8] = {pb0.x,pb0.y,pb0.z,pb0.w,pb1.x,pb1.y,pb1.z,pb1.w};
        uint32_t* aw = sAx[0][j];
        uint32_t* bw = sBx[0][nb];
#pragma unroll
        for (int c = 0; c < 4; c++) {
            int ph = (4 * g + c) ^ swzA;
            aw[ph * 4 + hi + 2 * hf] = h2pack(va[2*c], va[2*c+1]);
            bw[(ph ^ nbx) * 2 + hf]  = h2pack(vb[2*c], vb[2*c+1]);
        }
    }
    __syncthreads();

    int physC = lane ^ ((lane >> 3) & 3);

    for (int it = 0; it < nIter; it++) {
        int cur = it & 1;
        bool more = (it + 1) < nIter;
        if (more) {
            long ko = (long)(it + 1) * BKH;
            pa0 = *(const float4*)(Ap + ko); pa1 = *(const float4*)(Ap + ko + 4);
            pb0 = *(const float4*)(Bp + ko); pb1 = *(const float4*)(Bp + ko + 4);
        }

        {
            float4 af[4]; float2 bf[4];
#pragma unroll
            for (int mi = 0; mi < 4; mi++)
                af[mi] = ((const float4*)sAx[cur][bA0 + mi])[physC];
#pragma unroll
            for (int ni = 0; ni < 4; ni++) {
                int nb2 = nb0 + ni;
                bf[ni] = ((const float2*)sBx[cur][nb2])[physC ^ ((nb2 & 1) << 3)];
            }
#pragma unroll
            for (int mi = 0; mi < 4; mi++)
#pragma unroll
                for (int ni = 0; ni < 4; ni++)
                    mma_f16(acc[mi][ni], (const uint32_t*)&af[mi], (const uint32_t*)&bf[ni]);
        }

        if (more) {
            int nxt = cur ^ 1;
            float va[8] = {pa0.x,pa0.y,pa0.z,pa0.w,pa1.x,pa1.y,pa1.z,pa1.w};
            float vb[8] = {pb0.x,pb0.y,pb0.z,pb0.w,pb1.x,pb1.y,pb1.z,pb1.w};
            uint32_t* aw = sAx[nxt][j];
            uint32_t* bw = sBx[nxt][nb];
#pragma unroll
            for (int c = 0; c < 4; c++) {
                int ph = (4 * g + c) ^ swzA;
                aw[ph * 4 + hi + 2 * hf] = h2pack(va[2*c], va[2*c+1]);
                bw[(ph ^ nbx) * 2 + hf]  = h2pack(vb[2*c], vb[2*c+1]);
            }
        }
        __syncthreads();
    }

    int ge = lane >> 2, c2 = (lane & 3) * 2;
#pragma unroll
    for (int mi = 0; mi < 4; mi++) {
#pragma unroll
        for (int ni = 0; ni < 4; ni++) {
            int gm = m0 + wm + mi * 16 + ge;
            int gn = n0 + wn + ni * 8 + c2;
            float v0 = acc[mi][ni][0], v1 = acc[mi][ni][1];
            float v2 = acc[mi][ni][2], v3 = acc[mi][ni][3];
            if (bias) {
                float b0 = bias[gn], b1 = bias[gn + 1];
                v0 += b0; v1 += b1; v2 += b0; v3 += b1;
            }
            if (doGelu) { v0 = gelu_f(v0); v1 = gelu_f(v1); v2 = gelu_f(v2); v3 = gelu_f(v3); }
            if (resid) {
                const float* r0p = resid + (long)gm * ldc + gn;
                const float* r1p = resid + (long)(gm + 8) * ldc + gn;
                v0 += r0p[0]; v1 += r0p[1]; v2 += r1p[0]; v3 += r1p[1];
            }
            *(float2*)(C + (long)gm * ldc + gn)       = make_float2(v0, v1);
            *(float2*)(C + (long)(gm + 8) * ldc + gn) = make_float2(v2, v3);
        }
    }
}

// ---------------- dedicated logits kernel (M=2, fp32, memory-bound) ----------
__global__ __launch_bounds__(256)
void logits_k(const float* __restrict__ fin,
              const float* __restrict__ Wemb,
              float* __restrict__ out)
{
    __shared__ float f0[Dc], f1[Dc];
    int tid = threadIdx.x;
    for (int i = tid; i < Dc; i += 256) { f0[i] = fin[i]; f1[i] = fin[Dc + i]; }
    __syncthreads();
    int warp = tid >> 5, lane = tid & 31;
    long v = (long)blockIdx.x * 8 + warp;
    if (v >= Vc) return;
    const float* w = Wemb + v * Dc;
    float d0 = 0.f, d1 = 0.f;
    for (int i = lane * 4; i < Dc; i += 128) {
        float4 wv = *(const float4*)(w + i);
        d0 += wv.x * f0[i] + wv.y * f0[i+1] + wv.z * f0[i+2] + wv.w * f0[i+3];
        d1 += wv.x * f1[i] + wv.y * f1[i+1] + wv.z * f1[i+2] + wv.w * f1[i+3];
    }
#pragma unroll
    for (int o = 16; o > 0; o >>= 1) {
        d0 += __shfl_xor_sync(0xffffffff, d0, o);
        d1 += __shfl_xor_sync(0xffffffff, d1, o);
    }
    if (lane == 0) { out[v] = d0; out[(long)Vc + v] = d1; }
}

// ---------------- host-side launch helper ----------------
static inline void launch_f16(const float* A, int lda,
                              const float* B, int ldb,
                              float* C, int ldc,
                              int M, int N, int K,
                              const float* bias, const float* resid, int gelu)
{
    dim3 g(N / BN, M / BM, 1);
    gemm_f16<<<g, 256>>>(A, lda, B, ldb, C, ldc, K, bias, resid, gelu);
}

extern "C" void kernel_launch(void* const* d_in, const int* in_sizes, int n_in,
                              void* d_out, int out_size)
{
    const int*   x    = (const int*)  d_in[0];
    const float* Wemb = (const float*)d_in[1];
    const float* pos  = (const float*)d_in[2];
    const float* Wq   = (const float*)d_in[3];
    const float* Wk   = (const float*)d_in[4];
    const float* Wv   = (const float*)d_in[5];
    const float* Wo   = (const float*)d_in[6];
    const float* bo   = (const float*)d_in[7];
    const float* n1s  = (const float*)d_in[8];
    const float* n1b  = (const float*)d_in[9];
    const float* n2s  = (const float*)d_in[10];
    const float* n2b  = (const float*)d_in[11];
    const float* W1   = (const float*)d_in[12];
    const float* b1   = (const float*)d_in[13];
    const float* W2   = (const float*)d_in[14];
    const float* b2   = (const float*)d_in[15];
    const float* fs   = (const float*)d_in[16];
    const float* fb   = (const float*)d_in[17];
    float* out = (float*)d_out;

    float *h, *xn, *q, *k, *v, *ctx, *ff, *fin;
    cudaGetSymbolAddress((void**)&h,   g_h);
    cudaGetSymbolAddress((void**)&xn,  g_xn);
    cudaGetSymbolAddress((void**)&q,   g_q);
    cudaGetSymbolAddress((void**)&k,   g_k);
    cudaGetSymbolAddress((void**)&v,   g_v);
    cudaGetSymbolAddress((void**)&ctx, g_ctx);
    cudaGetSymbolAddress((void**)&ff,  g_ff);
    cudaGetSymbolAddress((void**)&fin, g_fin);

    const long TD = (long)Tc * Dc;

    {
        long n = (long)BTc * Dc;
        embed_k<<<(unsigned)((n + 255) / 256), 256>>>(x, Wemb, pos, h);
    }

    for (int l = 0; l < Lc; l++) {
        const float* Wql = Wq + (long)l * Dc * Dc;
        const float* Wkl = Wk + (long)l * Dc * Dc;
        const float* Wvl = Wv + (long)l * Dc * Dc;
        const float* Wol = Wo + (long)l * Dc * Dc;
        const float* bol = bo + (long)l * Dc;
        const float* W1l = W1 + (long)l * DFFc * Dc;
        const float* b1l = b1 + (long)l * DFFc;
        const float* W2l = W2 + (long)l * Dc * DFFc;
        const float* b2l = b2 + (long)l * Dc;

        // LN1
        ln_k<<<BTc, 256>>>(h, Dc, xn, Dc, n1s + (long)l * Dc, n1b + (long)l * Dc);

        // Q,K,V = xn @ W^T  (fp16 tensor cores)
        launch_f16(xn, Dc, Wql, Dc, q, Dc, BTc, Dc, Dc, 0, 0, 0);
        launch_f16(xn, Dc, Wkl, Dc, k, Dc, BTc, Dc, Dc, 0, 0, 0);
        launch_f16(xn, Dc, Wvl, Dc, v, Dc, BTc, Dc, Dc, 0, 0, 0);

        // fused causal attention (fp16 mma)
        {
            dim3 fg(Tc / 128, Bc * Hc);
            flash_k<<<fg, 256>>>(q, k, v, ctx);
        }

        // h = h + ctx @ Wo^T + bo
        launch_f16(ctx, Dc, Wol, Dc, h, Dc, BTc, Dc, Dc, bol, h, 0);

        // LN2
        ln_k<<<BTc, 256>>>(h, Dc, xn, Dc, n2s + (long)l * Dc, n2b + (long)l * Dc);

        // ff = gelu(xn @ W1^T + b1)
        launch_f16(xn, Dc, W1l, Dc, ff, DFFc, BTc, DFFc, Dc, b1l, 0, 1);

        // h = h + ff @ W2^T + b2
        launch_f16(ff, DFFc, W2l, DFFc, h, Dc, BTc, Dc, DFFc, b2l, h, 0);
    }

    // final LN on the 2 last-token rows only
    ln_k<<<Bc, 256>>>(h + (long)(Tc - 1) * Dc, TD, fin, Dc, fs, fb);

    // logits (fp32, memory-bound dedicated kernel)
    logits_k<<<(Vc + 7) / 8, 256>>>(fin, Wemb, out);
}

// round 12
// speedup vs baseline: 2.7081x; 1.3189x over previous
#include <cuda_runtime.h>
#include <cuda_bf16.h>
#include <cuda_fp16.h>
#include <math.h>
#include <stdint.h>

// ---------------- problem constants ----------------
#define Bc   2
#define Tc   2048
#define Dc   1024
#define Hc   16
#define HDc  64
#define DFFc 4096
#define Lc   8
#define Vc   50257
#define BTc  (Bc*Tc)          // 4096
#define EPSc 1e-5f

// ---------------- static device scratch (no allocs allowed) ----------------
__device__ float  g_h  [BTc*Dc];
__device__ float  g_fin[Bc*Dc];
__device__ __half g_xnh [BTc*Dc];
__device__ __half g_qh  [BTc*Dc];
__device__ __half g_kh  [BTc*Dc];
__device__ __half g_vh  [BTc*Dc];
__device__ __half g_ctxh[BTc*Dc];
__device__ __half g_ffh [(long)BTc*DFFc];
// fp16 weights (converted once per launch)
__device__ __half g_wq16[(long)Lc*Dc*Dc];
__device__ __half g_wk16[(long)Lc*Dc*Dc];
__device__ __half g_wv16[(long)Lc*Dc*Dc];
__device__ __half g_wo16[(long)Lc*Dc*Dc];
__device__ __half g_w116[(long)Lc*DFFc*Dc];
__device__ __half g_w216[(long)Lc*DFFc*Dc];

// ---------------- helpers ----------------
__device__ __forceinline__ float gelu_f(float x) {
    const float c = 0.7978845608028654f;
    return 0.5f * x * (1.0f + tanhf(c * (x + 0.044715f * x * x * x)));
}
__device__ __forceinline__ void mma_f16(float* c, const uint32_t* a, const uint32_t* b) {
    asm volatile(
        "mma.sync.aligned.m16n8k16.row.col.f32.f16.f16.f32 "
        "{%0,%1,%2,%3}, {%4,%5,%6,%7}, {%8,%9}, {%0,%1,%2,%3};"
        : "+f"(c[0]), "+f"(c[1]), "+f"(c[2]), "+f"(c[3])
        : "r"(a[0]), "r"(a[1]), "r"(a[2]), "r"(a[3]), "r"(b[0]), "r"(b[1]));
}
__device__ __forceinline__ uint32_t h2pack(float a, float b) {
    __half2 h = __floats2half2_rn(a, b);
    return *(uint32_t*)&h;
}

// ---------------- fp32 -> fp16 conversion (weights, once per launch) --------
__global__ void cvtk(const float* __restrict__ s, __half* __restrict__ d, long n)
{
    long i = ((long)blockIdx.x * blockDim.x + threadIdx.x) * 4;
    if (i >= n) return;
    float4 v = *(const float4*)(s + i);
    uint2 o;
    o.x = h2pack(v.x, v.y);
    o.y = h2pack(v.z, v.w);
    *(uint2*)(d + i) = o;
}

// ---------------- embedding ----------------
__global__ void embed_k(const int* __restrict__ x,
                        const float* __restrict__ Wemb,
                        const float* __restrict__ pos,
                        float* __restrict__ h)
{
    long i = (long)blockIdx.x * blockDim.x + threadIdx.x;
    if (i >= (long)BTc * Dc) return;
    int row = (int)(i / Dc);
    int d   = (int)(i % Dc);
    int t   = row % Tc;
    int tok = x[row];
    h[i] = Wemb[(long)tok * Dc + d] + pos[(long)t * Dc + d];
}

// ---------------- layernorm (ddof=1, std+eps), fp16 or fp32 output ---------
__global__ void ln_k(const float* __restrict__ in, long inStride,
                     void* __restrict__ out, long outStride, int outHalf,
                     const float* __restrict__ sc, const float* __restrict__ sh)
{
    __shared__ float red[256];
    int r = blockIdx.x, tid = threadIdx.x;
    const float* x = in + (long)r * inStride;
    float xv[4];
    float s = 0.f;
#pragma unroll
    for (int i = 0; i < 4; i++) { xv[i] = x[tid + i * 256]; s += xv[i]; }
    red[tid] = s; __syncthreads();
    for (int st = 128; st > 0; st >>= 1) { if (tid < st) red[tid] += red[tid + st]; __syncthreads(); }
    float mean = red[0] * (1.0f / (float)Dc);
    __syncthreads();
    float v = 0.f;
#pragma unroll
    for (int i = 0; i < 4; i++) { float t = xv[i] - mean; v += t * t; }
    red[tid] = v; __syncthreads();
    for (int st = 128; st > 0; st >>= 1) { if (tid < st) red[tid] += red[tid + st]; __syncthreads(); }
    float inv = 1.0f / (sqrtf(red[0] / (float)(Dc - 1)) + EPSc);
#pragma unroll
    for (int i = 0; i < 4; i++) {
        int d = tid + i * 256;
        float o = sc[d] * ((xv[i] - mean) * inv) + sh[d];
        if (outHalf) ((__half*)out)[(long)r * outStride + d] = __float2half_rn(o);
        else         ((float*)out)[(long)r * outStride + d] = o;
    }
}

// =====================================================================
// flash_k v4 (full fp16 I/O): fused causal attention, q-tile 128 rows.
// 8 warps x 16 q-rows; k-tiles of 64. P register-direct.
// smem union: Q staging 18KB -> K 8KB | V 8KB.
// =====================================================================
__global__ __launch_bounds__(256)
void flash_k(const __half* __restrict__ Qg, const __half* __restrict__ Kg,
             const __half* __restrict__ Vg, __half* __restrict__ Og)
{
    __shared__ uint32_t usm[4608];           // 18432 B
    uint32_t* Qsh = usm;                     // [128][36]
    uint32_t* sKf = usm;                     // [4][8][64] = 8KB
    uint32_t* sVf = usm + 2048;              // [4][8][64] = 8KB

    int qt = (int)gridDim.x - 1 - blockIdx.x;   // reversed: long CTAs first
    int q0 = qt * 128;
    int z  = blockIdx.y;
    int b  = z / Hc, hh = z % Hc;
    long base = (long)b * Tc * Dc + (long)hh * HDc;
    const __half* Qb = Qg + base;
    const __half* Kb = Kg + base;
    const __half* Vb = Vg + base;
    __half* Ob = Og + base;

    int tid = threadIdx.x, lane = tid & 31, warp = tid >> 5;
    int g = lane >> 2, c = lane & 3;
    int physC = lane ^ ((lane >> 3) & 3);

    // ---- load Q tile (128 x 64 halves) into smem, stride 36 words ----
    {
        int kr = tid >> 1, half = tid & 1;
        const uint4* src = (const uint4*)(Qb + (long)(q0 + kr) * Dc + half * 32);
        uint32_t* dst = Qsh + kr * 36 + half * 16;
#pragma unroll
        for (int f = 0; f < 4; f++)
            *(uint4*)(dst + f * 4) = src[f];
    }
    __syncthreads();

    // ---- Q fragments (direct word loads) ----
    uint32_t qf[4][4];
    {
        int r0w = warp * 16 + g;
#pragma unroll
        for (int kb = 0; kb < 4; kb++) {
            int w = kb * 8 + c;
            qf[kb][0] = Qsh[r0w * 36 + w];
            qf[kb][1] = Qsh[(r0w + 8) * 36 + w];
            qf[kb][2] = Qsh[r0w * 36 + w + 4];
            qf[kb][3] = Qsh[(r0w + 8) * 36 + w + 4];
        }
    }
    __syncthreads();   // Q area about to be reused for K/V

    float oacc[8][4];
#pragma unroll
    for (int i = 0; i < 8; i++)
#pragma unroll
        for (int e = 0; e < 4; e++) oacc[i][e] = 0.f;
    float m0 = -1e30f, m1 = -1e30f, l0 = 0.f, l1 = 0.f;

    // staging roles
    bool isK = tid < 128;
    int t = isK ? tid : (tid - 128);
    // K role: n-row = t&63, k-quarter (32 halves) = t>>6 -> kb pair
    int nK  = t & 63;
    int kqK = t >> 6;
    int nbK = nK >> 3, gK = nK & 7;
    int swzK = (gK >> 1) & 3;
    int nbxK = (nbK & 1) << 3;
    const __half* KpBase = Kb + (long)nK * Dc + kqK * 32;
    // V role: k-row = t&63, col-half = t>>6
    int kV = t & 63;
    int chV = t >> 6;
    int kbV = kV >> 4, kkV = kV & 15;
    int cV  = (kkV & 7) >> 1, hfV = (kkV >> 3) & 1, loV = kkV & 1;
    const __half* VpBase = Vb + (long)kV * Dc + chV * 32;

    int nkt = 2 * qt + 2;
    for (int kt = 0; kt < nkt; kt++) {
        int k0 = kt * 64;

        if (isK) {
#pragma unroll
            for (int i = 0; i < 2; i++) {
                int kb = 2 * kqK + i;
                const uint4* ps = (const uint4*)(KpBase + (long)k0 * Dc + i * 16);
                uint4 u0 = ps[0], u1 = ps[1];
                const uint32_t* W0 = (const uint32_t*)&u0;
                const uint32_t* W1 = (const uint32_t*)&u1;
                uint32_t* dst = sKf + kb * 512 + nbK * 64;
#pragma unroll
                for (int cc = 0; cc < 4; cc++) {
                    int s = ((4 * gK + cc) ^ swzK) ^ nbxK;
                    dst[s * 2 + 0] = W0[cc];
                    dst[s * 2 + 1] = W1[cc];
                }
            }
        } else {
            const uint4* vp = (const uint4*)(VpBase + (long)k0 * Dc);
            uint32_t* dstK = sVf + kbV * 512;
#pragma unroll
            for (int u = 0; u < 4; u++) {
                uint4 vv = vp[u];
                const uint32_t* W = (const uint32_t*)&vv;
#pragma unroll
                for (int w = 0; w < 4; w++) {
                    __half2 h2 = *(__half2*)&W[w];
#pragma unroll
                    for (int hw = 0; hw < 2; hw++) {
                        int j = u * 8 + w * 2 + hw;
                        int n = chV * 32 + j;
                        int nb = n >> 3, gg = n & 7;
                        int s = ((4 * gg + cV) ^ ((gg >> 1) & 3)) ^ ((nb & 1) << 3);
                        __half* hp = (__half*)&dstK[nb * 64 + s * 2 + hfV];
                        hp[loV] = hw ? __high2half(h2) : __low2half(h2);
                    }
                }
            }
        }
        __syncthreads();

        bool active = (k0 <= q0 + warp * 16 + 15);
        if (active) {
            // ---- S = Q @ K^T ----
            float sacc[8][4];
#pragma unroll
            for (int i = 0; i < 8; i++)
#pragma unroll
                for (int e = 0; e < 4; e++) sacc[i][e] = 0.f;
#pragma unroll
            for (int kb = 0; kb < 4; kb++) {
#pragma unroll
                for (int nb = 0; nb < 8; nb++) {
                    uint2 bk = *(uint2*)&sKf[kb * 512 + nb * 64 +
                                             (physC ^ ((nb & 1) << 3)) * 2];
                    mma_f16(sacc[nb], qf[kb], &bk.x);
                }
            }

            // ---- mask, scale, online softmax ----
            int qr0 = q0 + warp * 16 + g;
            int qr1 = qr0 + 8;
            bool maskNeed = (k0 + 63 > q0 + warp * 16);
            float rm0 = -1e30f, rm1 = -1e30f;
#pragma unroll
            for (int ni = 0; ni < 8; ni++) {
#pragma unroll
                for (int e = 0; e < 4; e++) {
                    float vvv = sacc[ni][e] * 0.125f;
                    if (maskNeed) {
                        int kc = k0 + ni * 8 + c * 2 + (e & 1);
                        if (kc > ((e >= 2) ? qr1 : qr0)) vvv = -1e30f;
                    }
                    sacc[ni][e] = vvv;
                    if (e < 2) rm0 = fmaxf(rm0, vvv); else rm1 = fmaxf(rm1, vvv);
                }
            }
            rm0 = fmaxf(rm0, __shfl_xor_sync(0xffffffffu, rm0, 1));
            rm0 = fmaxf(rm0, __shfl_xor_sync(0xffffffffu, rm0, 2));
            rm1 = fmaxf(rm1, __shfl_xor_sync(0xffffffffu, rm1, 1));
            rm1 = fmaxf(rm1, __shfl_xor_sync(0xffffffffu, rm1, 2));
            float mn0 = fmaxf(m0, rm0), mn1 = fmaxf(m1, rm1);
            float sc0 = __expf(m0 - mn0), sc1 = __expf(m1 - mn1);
            float rs0 = 0.f, rs1 = 0.f;
#pragma unroll
            for (int ni = 0; ni < 8; ni++) {
#pragma unroll
                for (int e = 0; e < 4; e++) {
                    float ee = __expf(sacc[ni][e] - ((e < 2) ? mn0 : mn1));
                    sacc[ni][e] = ee;
                    if (e < 2) rs0 += ee; else rs1 += ee;
                }
            }
            rs0 += __shfl_xor_sync(0xffffffffu, rs0, 1);
            rs0 += __shfl_xor_sync(0xffffffffu, rs0, 2);
            rs1 += __shfl_xor_sync(0xffffffffu, rs1, 1);
            rs1 += __shfl_xor_sync(0xffffffffu, rs1, 2);
            l0 = l0 * sc0 + rs0;
            l1 = l1 * sc1 + rs1;
            m0 = mn0; m1 = mn1;
#pragma unroll
            for (int ni = 0; ni < 8; ni++) {
#pragma unroll
                for (int e = 0; e < 4; e++) oacc[ni][e] *= (e < 2) ? sc0 : sc1;
            }

            // ---- O += P @ V (P register-direct) ----
#pragma unroll
            for (int kb = 0; kb < 4; kb++) {
                uint32_t pf[4];
                pf[0] = h2pack(sacc[2 * kb][0],     sacc[2 * kb][1]);
                pf[1] = h2pack(sacc[2 * kb][2],     sacc[2 * kb][3]);
                pf[2] = h2pack(sacc[2 * kb + 1][0], sacc[2 * kb + 1][1]);
                pf[3] = h2pack(sacc[2 * kb + 1][2], sacc[2 * kb + 1][3]);
#pragma unroll
                for (int nb = 0; nb < 8; nb++) {
                    uint2 bv = *(uint2*)&sVf[kb * 512 + nb * 64 +
                                             (physC ^ ((nb & 1) << 3)) * 2];
                    mma_f16(oacc[nb], pf, &bv.x);
                }
            }
        }
        __syncthreads();
    }

    // ---- normalize + write ctx (fp16) ----
    float il0 = 1.f / l0, il1 = 1.f / l1;
    int r0 = q0 + warp * 16 + g;
#pragma unroll
    for (int ni = 0; ni < 8; ni++) {
        int d = ni * 8 + 2 * c;
        *(uint32_t*)(Ob + (long)r0 * Dc + d) =
            h2pack(oacc[ni][0] * il0, oacc[ni][1] * il0);
        *(uint32_t*)(Ob + (long)(r0 + 8) * Dc + d) =
            h2pack(oacc[ni][2] * il1, oacc[ni][3] * il1);
    }
}

// =====================================================================
// gemm_h: dense NT GEMM, fp16 operands in global, fp32 accum.
// 128x128 block, 8 warps of 64x32 tiles, BK=16, double-buffered.
// C = A[M,K] @ B[N,K]^T [+bias][gelu][+resid]; out fp16 or fp32.
// =====================================================================
#define BM 128
#define BN 128

__global__ __launch_bounds__(256, 2)
void gemm_h(const __half* __restrict__ A, int lda,
            const __half* __restrict__ B, int ldb,
            void* __restrict__ Cp, int ldc, int K,
            const float* __restrict__ bias,
            const float* __restrict__ resid, int doGelu, int outHalf)
{
    __shared__ uint32_t sAx[2][8][128];
    __shared__ uint32_t sBx[2][16][64];

    int m0 = blockIdx.y * BM, n0 = blockIdx.x * BN;
    int tid = threadIdx.x, lane = tid & 31, warp = tid >> 5;
    int wm = (warp & 1) * 64, wn = (warp >> 1) * 32;
    int bA0 = wm >> 4, nb0 = wn >> 3;

    float acc[4][4][4];
#pragma unroll
    for (int i = 0; i < 4; i++)
#pragma unroll
        for (int jx = 0; jx < 4; jx++)
#pragma unroll
            for (int e = 0; e < 4; e++) acc[i][jx][e] = 0.f;

    int r  = tid >> 1, hf = tid & 1;
    int j  = r >> 4, nb = r >> 3, g = r & 7, hi = (r >> 3) & 1;
    int swzA = (g >> 1) & 3;
    int nbx  = (nb & 1) << 3;
    const __half* Ap = A + (long)(m0 + r) * lda + hf * 8;
    const __half* Bp = B + (long)(n0 + r) * ldb + hf * 8;

    int nIter = K / 16;

    uint4 pa = *(const uint4*)Ap;
    uint4 pb = *(const uint4*)Bp;

    {
        const uint32_t* WA = (const uint32_t*)&pa;
        const uint32_t* WB = (const uint32_t*)&pb;
        uint32_t* aw = sAx[0][j];
        uint32_t* bw = sBx[0][nb];
#pragma unroll
        for (int c = 0; c < 4; c++) {
            int ph = (4 * g + c) ^ swzA;
            aw[ph * 4 + hi + 2 * hf] = WA[c];
            bw[(ph ^ nbx) * 2 + hf]  = WB[c];
        }
    }
    __syncthreads();

    int physC = lane ^ ((lane >> 3) & 3);

    for (int it = 0; it < nIter; it++) {
        int cur = it & 1;
        bool more = (it + 1) < nIter;
        if (more) {
            long ko = (long)(it + 1) * 16;
            pa = *(const uint4*)(Ap + ko);
            pb = *(const uint4*)(Bp + ko);
        }

        {
            float4 af[4]; float2 bf[4];
#pragma unroll
            for (int mi = 0; mi < 4; mi++)
                af[mi] = ((const float4*)sAx[cur][bA0 + mi])[physC];
#pragma unroll
            for (int ni = 0; ni < 4; ni++) {
                int nb2 = nb0 + ni;
                bf[ni] = ((const float2*)sBx[cur][nb2])[physC ^ ((nb2 & 1) << 3)];
            }
#pragma unroll
            for (int mi = 0; mi < 4; mi++)
#pragma unroll
                for (int ni = 0; ni < 4; ni++)
                    mma_f16(acc[mi][ni], (const uint32_t*)&af[mi], (const uint32_t*)&bf[ni]);
        }

        if (more) {
            int nxt = cur ^ 1;
            const uint32_t* WA = (const uint32_t*)&pa;
            const uint32_t* WB = (const uint32_t*)&pb;
            uint32_t* aw = sAx[nxt][j];
            uint32_t* bw = sBx[nxt][nb];
#pragma unroll
            for (int c = 0; c < 4; c++) {
                int ph = (4 * g + c) ^ swzA;
                aw[ph * 4 + hi + 2 * hf] = WA[c];
                bw[(ph ^ nbx) * 2 + hf]  = WB[c];
            }
        }
        __syncthreads();
    }

    // ---- epilogue ----
    int ge = lane >> 2, c2 = (lane & 3) * 2;
#pragma unroll
    for (int mi = 0; mi < 4; mi++) {
#pragma unroll
        for (int ni = 0; ni < 4; ni++) {
            int gm = m0 + wm + mi * 16 + ge;
            int gn = n0 + wn + ni * 8 + c2;
            float v0 = acc[mi][ni][0], v1 = acc[mi][ni][1];
            float v2 = acc[mi][ni][2], v3 = acc[mi][ni][3];
            if (bias) {
                float b0 = bias[gn], b1 = bias[gn + 1];
                v0 += b0; v1 += b1; v2 += b0; v3 += b1;
            }
            if (doGelu) { v0 = gelu_f(v0); v1 = gelu_f(v1); v2 = gelu_f(v2); v3 = gelu_f(v3); }
            if (resid) {
                const float* r0p = resid + (long)gm * ldc + gn;
                const float* r1p = resid + (long)(gm + 8) * ldc + gn;
                v0 += r0p[0]; v1 += r0p[1]; v2 += r1p[0]; v3 += r1p[1];
            }
            if (outHalf) {
                __half* C = (__half*)Cp;
                *(uint32_t*)(C + (long)gm * ldc + gn)       = h2pack(v0, v1);
                *(uint32_t*)(C + (long)(gm + 8) * ldc + gn) = h2pack(v2, v3);
            } else {
                float* C = (float*)Cp;
                *(float2*)(C + (long)gm * ldc + gn)       = make_float2(v0, v1);
                *(float2*)(C + (long)(gm + 8) * ldc + gn) = make_float2(v2, v3);
            }
        }
    }
}

// ---------------- dedicated logits kernel (M=2, fp32, memory-bound) ----------
__global__ __launch_bounds__(256)
void logits_k(const float* __restrict__ fin,
              const float* __restrict__ Wemb,
              float* __restrict__ out)
{
    __shared__ float f0[Dc], f1[Dc];
    int tid = threadIdx.x;
    for (int i = tid; i < Dc; i += 256) { f0[i] = fin[i]; f1[i] = fin[Dc + i]; }
    __syncthreads();
    int warp = tid >> 5, lane = tid & 31;
    long v = (long)blockIdx.x * 8 + warp;
    if (v >= Vc) return;
    const float* w = Wemb + v * Dc;
    float d0 = 0.f, d1 = 0.f;
    for (int i = lane * 4; i < Dc; i += 128) {
        float4 wv = *(const float4*)(w + i);
        d0 += wv.x * f0[i] + wv.y * f0[i+1] + wv.z * f0[i+2] + wv.w * f0[i+3];
        d1 += wv.x * f1[i] + wv.y * f1[i+1] + wv.z * f1[i+2] + wv.w * f1[i+3];
    }
#pragma unroll
    for (int o = 16; o > 0; o >>= 1) {
        d0 += __shfl_xor_sync(0xffffffff, d0, o);
        d1 += __shfl_xor_sync(0xffffffff, d1, o);
    }
    if (lane == 0) { out[v] = d0; out[(long)Vc + v] = d1; }
}

// ---------------- host-side launch helpers ----------------
static inline void launch_h(const __half* A, int lda, const __half* B, int ldb,
                            void* C, int ldc, int M, int N, int K,
                            const float* bias, const float* resid,
                            int gelu, int outHalf)
{
    dim3 g(N / BN, M / BM, 1);
    gemm_h<<<g, 256>>>(A, lda, B, ldb, C, ldc, K, bias, resid, gelu, outHalf);
}
static inline void launch_cvt(const float* s, __half* d, long n)
{
    long blocks = (n / 4 + 255) / 256;
    cvtk<<<(unsigned)blocks, 256>>>(s, d, n);
}

extern "C" void kernel_launch(void* const* d_in, const int* in_sizes, int n_in,
                              void* d_out, int out_size)
{
    const int*   x    = (const int*)  d_in[0];
    const float* Wemb = (const float*)d_in[1];
    const float* pos  = (const float*)d_in[2];
    const float* Wq   = (const float*)d_in[3];
    const float* Wk   = (const float*)d_in[4];
    const float* Wv   = (const float*)d_in[5];
    const float* Wo   = (const float*)d_in[6];
    const float* bo   = (const float*)d_in[7];
    const float* n1s  = (const float*)d_in[8];
    const float* n1b  = (const float*)d_in[9];
    const float* n2s  = (const float*)d_in[10];
    const float* n2b  = (const float*)d_in[11];
    const float* W1   = (const float*)d_in[12];
    const float* b1   = (const float*)d_in[13];
    const float* W2   = (const float*)d_in[14];
    const float* b2   = (const float*)d_in[15];
    const float* fs   = (const float*)d_in[16];
    const float* fb   = (const float*)d_in[17];
    float* out = (float*)d_out;

    float  *h, *fin;
    __half *xnh, *qh, *kh, *vh, *ctxh, *ffh;
    __half *wq16, *wk16, *wv16, *wo16, *w116, *w216;
    cudaGetSymbolAddress((void**)&h,    g_h);
    cudaGetSymbolAddress((void**)&fin,  g_fin);
    cudaGetSymbolAddress((void**)&xnh,  g_xnh);
    cudaGetSymbolAddress((void**)&qh,   g_qh);
    cudaGetSymbolAddress((void**)&kh,   g_kh);
    cudaGetSymbolAddress((void**)&vh,   g_vh);
    cudaGetSymbolAddress((void**)&ctxh, g_ctxh);
    cudaGetSymbolAddress((void**)&ffh,  g_ffh);
    cudaGetSymbolAddress((void**)&wq16, g_wq16);
    cudaGetSymbolAddress((void**)&wk16, g_wk16);
    cudaGetSymbolAddress((void**)&wv16, g_wv16);
    cudaGetSymbolAddress((void**)&wo16, g_wo16);
    cudaGetSymbolAddress((void**)&w116, g_w116);
    cudaGetSymbolAddress((void**)&w216, g_w216);

    const long TD = (long)Tc * Dc;
    const long DD = (long)Dc * Dc;
    const long FD = (long)DFFc * Dc;

    // weights -> fp16 (once per launch; graph-capturable)
    launch_cvt(Wq, wq16, (long)Lc * DD);
    launch_cvt(Wk, wk16, (long)Lc * DD);
    launch_cvt(Wv, wv16, (long)Lc * DD);
    launch_cvt(Wo, wo16, (long)Lc * DD);
    launch_cvt(W1, w116, (long)Lc * FD);
    launch_cvt(W2, w216, (long)Lc * FD);

    {
        long n = (long)BTc * Dc;
        embed_k<<<(unsigned)((n + 255) / 256), 256>>>(x, Wemb, pos, h);
    }

    for (int l = 0; l < Lc; l++) {
        const float* bol = bo + (long)l * Dc;
        const float* b1l = b1 + (long)l * DFFc;
        const float* b2l = b2 + (long)l * Dc;

        // LN1 -> fp16
        ln_k<<<BTc, 256>>>(h, Dc, xnh, Dc, 1, n1s + (long)l * Dc, n1b + (long)l * Dc);

        // Q,K,V = xn @ W^T  (fp16 in/out)
        launch_h(xnh, Dc, wq16 + l * DD, Dc, qh, Dc, BTc, Dc, Dc, 0, 0, 0, 1);
        launch_h(xnh, Dc, wk16 + l * DD, Dc, kh, Dc, BTc, Dc, Dc, 0, 0, 0, 1);
        launch_h(xnh, Dc, wv16 + l * DD, Dc, vh, Dc, BTc, Dc, Dc, 0, 0, 0, 1);

        // fused causal attention (fp16 I/O)
        {
            dim3 fg(Tc / 128, Bc * Hc);
            flash_k<<<fg, 256>>>(qh, kh, vh, ctxh);
        }

        // h = h + ctx @ Wo^T + bo  (fp32 out)
        launch_h(ctxh, Dc, wo16 + l * DD, Dc, h, Dc, BTc, Dc, Dc, bol, h, 0, 0);

        // LN2 -> fp16
        ln_k<<<BTc, 256>>>(h, Dc, xnh, Dc, 1, n2s + (long)l * Dc, n2b + (long)l * Dc);

        // ff = gelu(xn @ W1^T + b1)  (fp16 out)
        launch_h(xnh, Dc, w116 + l * FD, Dc, ffh, DFFc, BTc, DFFc, Dc, b1l, 0, 1, 1);

        // h = h + ff @ W2^T + b2  (fp32 out)
        launch_h(ffh, DFFc, w216 + l * FD, DFFc, h, Dc, BTc, Dc, DFFc, b2l, h, 0, 0);
    }

    // final LN on the 2 last-token rows only -> fp32
    ln_k<<<Bc, 256>>>(h + (long)(Tc - 1) * Dc, TD, fin, Dc, 0, fs, fb);

    // logits (fp32, memory-bound dedicated kernel)
    logits_k<<<(Vc + 7) / 8, 256>>>(fin, Wemb, out);
}